// round 1
// baseline (speedup 1.0000x reference)
#include <cuda_runtime.h>
#include <math.h>

// Problem constants (fixed-shape problem)
#define NN 40000      // nodes
#define NE 150000     // edges per type
#define HH 4          // heads
#define DD 128        // per-head dim
#define FF 512        // HH*DD
#define NOUT 2983

// ---------------------------------------------------------------------------
// Scratch (device globals; no allocation allowed)
// ---------------------------------------------------------------------------
__device__ float g_feat[(size_t)NN * FF];
__device__ float g_acc [(size_t)NN * FF];
__device__ float g_h1  [(size_t)NN * FF];
__device__ float g_h2  [(size_t)NN * FF];
__device__ float g_el  [NN * HH];
__device__ float g_er  [NN * HH];
__device__ float g_m   [NN * HH];
__device__ float g_s   [NN * HH];
__device__ float g_w   [NE * HH];

// ---------------------------------------------------------------------------
// Generic SGEMM: C[M,N] = A[M,K] @ B[K,N]  (row-major), optional bias add.
// 64x64 tile, BK=16, 256 threads, 4x4 per thread.
// Requires K % 16 == 0 and K % 4 == 0 (true here: 1024/512).
// N is fully guarded (handles N=2983).
// ---------------------------------------------------------------------------
template <bool ADD_BIAS>
__global__ __launch_bounds__(256)
void sgemm64(const float* __restrict__ A, const float* __restrict__ B,
             float* __restrict__ C, int M, int N, int K,
             const float* __restrict__ bias)
{
    __shared__ float As[16][64];
    __shared__ float Bs[16][64];

    const int bm = blockIdx.y * 64;
    const int bn = blockIdx.x * 64;
    const int t  = threadIdx.x;
    const int tx = t & 15;
    const int ty = t >> 4;

    float acc[4][4] = {};

    for (int k0 = 0; k0 < K; k0 += 16) {
        // Load A tile: 64 rows x 16 k. Each thread loads one float4 (4 consecutive k).
        {
            int idx = t * 4;
            int row = idx >> 4;           // 0..63
            int col = idx & 15;           // 0,4,8,12
            int m = bm + row;
            float4 v = make_float4(0.f, 0.f, 0.f, 0.f);
            if (m < M)
                v = *reinterpret_cast<const float4*>(A + (size_t)m * K + k0 + col);
            As[col + 0][row] = v.x;
            As[col + 1][row] = v.y;
            As[col + 2][row] = v.z;
            As[col + 3][row] = v.w;
        }
        // Load B tile: 16 k x 64 n. Scalar guarded loads (N may be ragged).
        {
            int idx = t * 4;
            int row = idx >> 6;           // 0..15
            int col = idx & 63;           // 0,4,...,60
            int kk = k0 + row;
            const float* Brow = B + (size_t)kk * N;
            #pragma unroll
            for (int j = 0; j < 4; j++) {
                int n = bn + col + j;
                Bs[row][col + j] = (n < N) ? Brow[n] : 0.f;
            }
        }
        __syncthreads();

        #pragma unroll
        for (int k = 0; k < 16; k++) {
            float a[4], b[4];
            *reinterpret_cast<float4*>(a) = *reinterpret_cast<const float4*>(&As[k][ty * 4]);
            *reinterpret_cast<float4*>(b) = *reinterpret_cast<const float4*>(&Bs[k][tx * 4]);
            #pragma unroll
            for (int i = 0; i < 4; i++)
                #pragma unroll
                for (int j = 0; j < 4; j++)
                    acc[i][j] = fmaf(a[i], b[j], acc[i][j]);
        }
        __syncthreads();
    }

    #pragma unroll
    for (int i = 0; i < 4; i++) {
        int m = bm + ty * 4 + i;
        if (m >= M) continue;
        #pragma unroll
        for (int j = 0; j < 4; j++) {
            int n = bn + tx * 4 + j;
            if (n >= N) continue;
            float v = acc[i][j];
            if (ADD_BIAS) v += bias[n];
            C[(size_t)m * N + n] = v;
        }
    }
}

// ---------------------------------------------------------------------------
// Attention logits: el[n,h] = <feat[n,h,:], al[h,:]>, er likewise.
// One warp per (node, head).
// ---------------------------------------------------------------------------
__global__ void logits_kernel(const float* __restrict__ feat,
                              const float* __restrict__ al,
                              const float* __restrict__ ar,
                              float* __restrict__ el, float* __restrict__ er)
{
    int gw   = (blockIdx.x * blockDim.x + threadIdx.x) >> 5;
    int lane = threadIdx.x & 31;
    if (gw >= NN * HH) return;
    int n = gw >> 2;
    int h = gw & 3;

    float4 fv = reinterpret_cast<const float4*>(feat + (size_t)n * FF + h * DD)[lane];
    float4 av = reinterpret_cast<const float4*>(al + h * DD)[lane];
    float4 rv = reinterpret_cast<const float4*>(ar + h * DD)[lane];

    float dl = fv.x * av.x + fv.y * av.y + fv.z * av.z + fv.w * av.w;
    float dr = fv.x * rv.x + fv.y * rv.y + fv.z * rv.z + fv.w * rv.w;
    #pragma unroll
    for (int o = 16; o; o >>= 1) {
        dl += __shfl_xor_sync(0xFFFFFFFFu, dl, o);
        dr += __shfl_xor_sync(0xFFFFFFFFu, dr, o);
    }
    if (lane == 0) { el[gw] = dl; er[gw] = dr; }
}

// ---------------------------------------------------------------------------
// Segment softmax helpers
// ---------------------------------------------------------------------------
__device__ __forceinline__ void atomicMaxF(float* addr, float v)
{
    // Combined signed-int / unsigned-int monotone encoding; init must be -inf.
    if (v >= 0.f) atomicMax(reinterpret_cast<int*>(addr), __float_as_int(v));
    else          atomicMin(reinterpret_cast<unsigned int*>(addr), __float_as_uint(v));
}

__global__ void init_m_kernel(float* __restrict__ m)
{
    int i = blockIdx.x * blockDim.x + threadIdx.x;
    if (i < NN * HH) m[i] = -INFINITY;
}

__global__ void edge_max_kernel(const int* __restrict__ src, const int* __restrict__ dst,
                                const float* __restrict__ el, const float* __restrict__ er,
                                float* __restrict__ w, float* __restrict__ m)
{
    int i = blockIdx.x * blockDim.x + threadIdx.x;
    if (i >= NE * HH) return;
    int e = i >> 2;
    int h = i & 3;
    float v = el[src[e] * HH + h] + er[dst[e] * HH + h];
    v = (v > 0.f) ? v : 0.2f * v;     // leaky_relu 0.2
    w[i] = v;
    atomicMaxF(&m[dst[e] * HH + h], v);
}

__global__ void edge_exp_kernel(const int* __restrict__ dst,
                                float* __restrict__ w,
                                const float* __restrict__ m,
                                float* __restrict__ s)
{
    int i = blockIdx.x * blockDim.x + threadIdx.x;
    if (i >= NE * HH) return;
    int e = i >> 2;
    int h = i & 3;
    int d = dst[e] * HH + h;
    float ww = expf(w[i] - m[d]);
    w[i] = ww;
    atomicAdd(&s[d], ww);
}

// ---------------------------------------------------------------------------
// Message aggregation: one warp per (edge, head); float4 gather + atomic scatter.
// ---------------------------------------------------------------------------
__global__ void edge_aggr_kernel(const int* __restrict__ src, const int* __restrict__ dst,
                                 const float* __restrict__ feat,
                                 const float* __restrict__ w, const float* __restrict__ s,
                                 float* __restrict__ out)
{
    int gw   = (blockIdx.x * blockDim.x + threadIdx.x) >> 5;
    int lane = threadIdx.x & 31;
    if (gw >= NE * HH) return;
    int e = gw >> 2;
    int h = gw & 3;
    int sn = src[e];
    int dn = dst[e];
    float a = w[gw] / s[dn * HH + h];

    float4 v = reinterpret_cast<const float4*>(feat + (size_t)sn * FF + h * DD)[lane];
    float* o = out + (size_t)dn * FF + h * DD + lane * 4;
    atomicAdd(o + 0, v.x * a);
    atomicAdd(o + 1, v.y * a);
    atomicAdd(o + 2, v.z * a);
    atomicAdd(o + 3, v.w * a);
}

// ---------------------------------------------------------------------------
// Per-type epilogue: out (+)= leaky_relu(acc + b_t). Activation is PER TYPE
// before the hetero sum, matching the reference.
// ---------------------------------------------------------------------------
__global__ void combine_kernel(const float* __restrict__ acc, const float* __restrict__ bias,
                               float* __restrict__ out, int activate, int first)
{
    int i = blockIdx.x * blockDim.x + threadIdx.x;
    if (i >= NN * FF) return;
    int c = i & (FF - 1);
    float v = acc[i] + bias[c];
    if (activate) v = (v > 0.f) ? v : 0.01f * v;
    out[i] = first ? v : out[i] + v;
}

// ---------------------------------------------------------------------------
// Launch
// ---------------------------------------------------------------------------
extern "C" void kernel_launch(void* const* d_in, const int* in_sizes, int n_in,
                              void* d_out, int out_size)
{
    const float* x = (const float*)d_in[0];
    const int* src[2] = {(const int*)d_in[1], (const int*)d_in[3]};
    const int* dst[2] = {(const int*)d_in[2], (const int*)d_in[4]};
    const float* W [3] = {(const float*)d_in[5],  (const float*)d_in[9],  (const float*)d_in[13]};
    const float* al[3] = {(const float*)d_in[6],  (const float*)d_in[10], (const float*)d_in[14]};
    const float* ar[3] = {(const float*)d_in[7],  (const float*)d_in[11], (const float*)d_in[15]};
    const float* bb[3] = {(const float*)d_in[8],  (const float*)d_in[12], (const float*)d_in[16]};
    const float* Wout = (const float*)d_in[17];
    const float* bout = (const float*)d_in[18];
    float* out = (float*)d_out;

    float *feat, *acc, *h1, *h2, *el, *er, *m, *s, *w;
    cudaGetSymbolAddress((void**)&feat, g_feat);
    cudaGetSymbolAddress((void**)&acc,  g_acc);
    cudaGetSymbolAddress((void**)&h1,   g_h1);
    cudaGetSymbolAddress((void**)&h2,   g_h2);
    cudaGetSymbolAddress((void**)&el,   g_el);
    cudaGetSymbolAddress((void**)&er,   g_er);
    cudaGetSymbolAddress((void**)&m,    g_m);
    cudaGetSymbolAddress((void**)&s,    g_s);
    cudaGetSymbolAddress((void**)&w,    g_w);

    const int nhThreads = NN * HH;                    // 160000
    const int ehThreads = NE * HH;                    // 600000
    const int nhBlocks  = (nhThreads + 255) / 256;
    const int ehBlocks  = (ehThreads + 255) / 256;
    const int lgBlocks  = (nhThreads * 32 + 255) / 256;   // warp per (n,h)
    const int agBlocks  = (ehThreads + 7) / 8;            // warp per (e,h), 8 warps/block
    const int cbBlocks  = ((size_t)NN * FF + 255) / 256;

    const float* hin = x;
    float* houts[3] = {h1, h2, h1};
    const int Ks[3] = {1024, 512, 512};

    for (int L = 0; L < 3; L++) {
        float* hout = houts[L];
        for (int t = 0; t < 2; t++) {
            const float* Wt = W[L] + (size_t)t * Ks[L] * FF;
            dim3 grid(FF / 64, NN / 64);
            sgemm64<false><<<grid, 256>>>(hin, Wt, feat, NN, FF, Ks[L], nullptr);

            logits_kernel<<<lgBlocks, 256>>>(feat, al[L] + t * FF, ar[L] + t * FF, el, er);

            init_m_kernel<<<nhBlocks, 256>>>(m);
            cudaMemsetAsync(s, 0, (size_t)NN * HH * sizeof(float), 0);

            edge_max_kernel<<<ehBlocks, 256>>>(src[t], dst[t], el, er, w, m);
            edge_exp_kernel<<<ehBlocks, 256>>>(dst[t], w, m, s);

            cudaMemsetAsync(acc, 0, (size_t)NN * FF * sizeof(float), 0);
            edge_aggr_kernel<<<agBlocks, 256>>>(src[t], dst[t], feat, w, s, acc);

            combine_kernel<<<cbBlocks, 256>>>(acc, bb[L] + t * FF, hout,
                                              (L < 2) ? 1 : 0, (t == 0) ? 1 : 0);
        }
        hin = hout;
    }

    dim3 gridF((NOUT + 63) / 64, NN / 64);
    sgemm64<true><<<gridF, 256>>>(hin, Wout, out, NN, NOUT, FF, bout);
}

// round 2
// speedup vs baseline: 2.2455x; 2.2455x over previous
#include <cuda_runtime.h>
#include <math.h>
#include <stdint.h>

// Problem constants (fixed-shape problem)
#define NN 40000      // nodes
#define NE 150000     // edges per type
#define HH 4          // heads
#define DD 128        // per-head dim
#define FF 512        // HH*DD
#define NOUT 2983

// ---------------------------------------------------------------------------
// Scratch (device globals; no allocation allowed)
// ---------------------------------------------------------------------------
__device__ float g_feat[(size_t)NN * FF];
__device__ float g_acc [(size_t)NN * FF];
__device__ float g_h1  [(size_t)NN * FF];
__device__ float g_h2  [(size_t)NN * FF];
__device__ float g_el  [NN * HH];
__device__ float g_er  [NN * HH];
__device__ float g_m   [NN * HH];
__device__ float g_s   [NN * HH];
__device__ float g_w   [NE * HH];

// ---------------------------------------------------------------------------
// TF32 tensor-core GEMM: C[M,N] = A[M,K] @ B[K,N] (row-major), optional bias.
// BM=128, BN=128, BK=16, 256 threads (8 warps), warp tile 64x32,
// mma.sync.aligned.m16n8k8.row.col.f32.tf32.tf32.f32.
// K % 16 == 0 required (1024/512 ok). M and N fully guarded.
// ---------------------------------------------------------------------------
#define BM 128
#define BN 128
#define BK 16
#define AS_LD 20      // 16 + 4 pad: conflict-free a-frag loads
#define BS_LD 132     // 128 + 4 pad: conflict-free b-frag loads

__device__ __forceinline__ float to_tf32(float x)
{
    unsigned r;
    asm("cvt.rna.tf32.f32 %0, %1;" : "=r"(r) : "f"(x));
    return __uint_as_float(r);
}

__device__ __forceinline__ void mma_tf32(float c[4],
                                         float a0, float a1, float a2, float a3,
                                         float b0, float b1)
{
    asm volatile(
        "mma.sync.aligned.m16n8k8.row.col.f32.tf32.tf32.f32 "
        "{%0,%1,%2,%3}, {%4,%5,%6,%7}, {%8,%9}, {%0,%1,%2,%3};\n"
        : "+f"(c[0]), "+f"(c[1]), "+f"(c[2]), "+f"(c[3])
        : "r"(__float_as_uint(a0)), "r"(__float_as_uint(a1)),
          "r"(__float_as_uint(a2)), "r"(__float_as_uint(a3)),
          "r"(__float_as_uint(b0)), "r"(__float_as_uint(b1)));
}

template <bool ADD_BIAS>
__global__ __launch_bounds__(256)
void gemm_tf32(const float* __restrict__ A, const float* __restrict__ B,
               float* __restrict__ C, int M, int N, int K,
               const float* __restrict__ bias)
{
    __shared__ float As[2][BM][AS_LD];
    __shared__ float Bs[2][BK][BS_LD];

    const int tid  = threadIdx.x;
    const int wid  = tid >> 5;
    const int lane = tid & 31;
    const int wm   = wid & 1;          // warp row  (0..1) -> 64 rows
    const int wn   = wid >> 1;         // warp col  (0..3) -> 32 cols
    const int g    = lane >> 2;        // group 0..7
    const int q    = lane & 3;         // quad  0..3

    const int bm = blockIdx.y * BM;
    const int bn = blockIdx.x * BN;

    float c[4][4][4];
    #pragma unroll
    for (int i = 0; i < 4; i++)
        #pragma unroll
        for (int j = 0; j < 4; j++)
            #pragma unroll
            for (int r = 0; r < 4; r++) c[i][j][r] = 0.f;

    // A-load mapping: 512 float4s / 256 threads = 2 each
    const int af0   = tid * 2;                 // float4 index base
    // B-load mapping: coalesced scalar, 2048 / 256 = 8 each
    const int bc    = tid & 127;               // col within tile
    const int br0   = (tid >> 7) * 8;          // row base: 0 or 8

    float4 aReg[2];
    float  bReg[8];

    const int nt = K / BK;

    // ---- prologue: load tile 0 ----
    {
        #pragma unroll
        for (int i = 0; i < 2; i++) {
            int f   = af0 + i;
            int row = f >> 2;
            int kc  = (f & 3) * 4;
            int m   = bm + row;
            aReg[i] = make_float4(0.f, 0.f, 0.f, 0.f);
            if (m < M)
                aReg[i] = *reinterpret_cast<const float4*>(A + (size_t)m * K + kc);
        }
        int n = bn + bc;
        #pragma unroll
        for (int j = 0; j < 8; j++)
            bReg[j] = (n < N) ? B[(size_t)(br0 + j) * N + n] : 0.f;

        #pragma unroll
        for (int i = 0; i < 2; i++) {
            int f   = af0 + i;
            int row = f >> 2;
            int kc  = (f & 3) * 4;
            As[0][row][kc + 0] = to_tf32(aReg[i].x);
            As[0][row][kc + 1] = to_tf32(aReg[i].y);
            As[0][row][kc + 2] = to_tf32(aReg[i].z);
            As[0][row][kc + 3] = to_tf32(aReg[i].w);
        }
        #pragma unroll
        for (int j = 0; j < 8; j++)
            Bs[0][br0 + j][bc] = to_tf32(bReg[j]);
    }
    __syncthreads();

    for (int t = 0; t < nt; t++) {
        const int cur = t & 1;
        const int nxt = cur ^ 1;
        const bool havenext = (t + 1 < nt);

        // ---- prefetch next tile into registers ----
        if (havenext) {
            int k0 = (t + 1) * BK;
            #pragma unroll
            for (int i = 0; i < 2; i++) {
                int f   = af0 + i;
                int row = f >> 2;
                int kc  = (f & 3) * 4;
                int m   = bm + row;
                aReg[i] = make_float4(0.f, 0.f, 0.f, 0.f);
                if (m < M)
                    aReg[i] = *reinterpret_cast<const float4*>(A + (size_t)m * K + k0 + kc);
            }
            int n = bn + bc;
            #pragma unroll
            for (int j = 0; j < 8; j++)
                bReg[j] = (n < N) ? B[(size_t)(k0 + br0 + j) * N + n] : 0.f;
        }

        // ---- compute on current buffer ----
        #pragma unroll
        for (int ks = 0; ks < 2; ks++) {
            const int kb = ks * 8;
            float a[4][4], b[4][2];
            #pragma unroll
            for (int mi = 0; mi < 4; mi++) {
                int r = wm * 64 + mi * 16 + g;
                a[mi][0] = As[cur][r    ][kb + q];
                a[mi][1] = As[cur][r + 8][kb + q];
                a[mi][2] = As[cur][r    ][kb + q + 4];
                a[mi][3] = As[cur][r + 8][kb + q + 4];
            }
            #pragma unroll
            for (int nj = 0; nj < 4; nj++) {
                int cn = wn * 32 + nj * 8 + g;
                b[nj][0] = Bs[cur][kb + q    ][cn];
                b[nj][1] = Bs[cur][kb + q + 4][cn];
            }
            #pragma unroll
            for (int mi = 0; mi < 4; mi++)
                #pragma unroll
                for (int nj = 0; nj < 4; nj++)
                    mma_tf32(c[mi][nj], a[mi][0], a[mi][1], a[mi][2], a[mi][3],
                             b[nj][0], b[nj][1]);
        }

        // ---- stage next tile into the other buffer ----
        if (havenext) {
            #pragma unroll
            for (int i = 0; i < 2; i++) {
                int f   = af0 + i;
                int row = f >> 2;
                int kc  = (f & 3) * 4;
                As[nxt][row][kc + 0] = to_tf32(aReg[i].x);
                As[nxt][row][kc + 1] = to_tf32(aReg[i].y);
                As[nxt][row][kc + 2] = to_tf32(aReg[i].z);
                As[nxt][row][kc + 3] = to_tf32(aReg[i].w);
            }
            #pragma unroll
            for (int j = 0; j < 8; j++)
                Bs[nxt][br0 + j][bc] = to_tf32(bReg[j]);
        }
        __syncthreads();
    }

    // ---- epilogue ----
    #pragma unroll
    for (int mi = 0; mi < 4; mi++) {
        int row0 = bm + wm * 64 + mi * 16 + g;
        #pragma unroll
        for (int nj = 0; nj < 4; nj++) {
            int col0 = bn + wn * 32 + nj * 8 + 2 * q;
            #pragma unroll
            for (int r = 0; r < 4; r++) {
                int row = row0 + (r >= 2 ? 8 : 0);
                int col = col0 + (r & 1);
                if (row < M && col < N) {
                    float v = c[mi][nj][r];
                    if (ADD_BIAS) v += bias[col];
                    C[(size_t)row * N + col] = v;
                }
            }
        }
    }
}

// ---------------------------------------------------------------------------
// Attention logits: el[n,h] = <feat[n,h,:], al[h,:]>, er likewise.
// One warp per (node, head).
// ---------------------------------------------------------------------------
__global__ void logits_kernel(const float* __restrict__ feat,
                              const float* __restrict__ al,
                              const float* __restrict__ ar,
                              float* __restrict__ el, float* __restrict__ er)
{
    int gw   = (blockIdx.x * blockDim.x + threadIdx.x) >> 5;
    int lane = threadIdx.x & 31;
    if (gw >= NN * HH) return;
    int n = gw >> 2;
    int h = gw & 3;

    float4 fv = reinterpret_cast<const float4*>(feat + (size_t)n * FF + h * DD)[lane];
    float4 av = reinterpret_cast<const float4*>(al + h * DD)[lane];
    float4 rv = reinterpret_cast<const float4*>(ar + h * DD)[lane];

    float dl = fv.x * av.x + fv.y * av.y + fv.z * av.z + fv.w * av.w;
    float dr = fv.x * rv.x + fv.y * rv.y + fv.z * rv.z + fv.w * rv.w;
    #pragma unroll
    for (int o = 16; o; o >>= 1) {
        dl += __shfl_xor_sync(0xFFFFFFFFu, dl, o);
        dr += __shfl_xor_sync(0xFFFFFFFFu, dr, o);
    }
    if (lane == 0) { el[gw] = dl; er[gw] = dr; }
}

// ---------------------------------------------------------------------------
// Segment softmax helpers
// ---------------------------------------------------------------------------
__device__ __forceinline__ void atomicMaxF(float* addr, float v)
{
    if (v >= 0.f) atomicMax(reinterpret_cast<int*>(addr), __float_as_int(v));
    else          atomicMin(reinterpret_cast<unsigned int*>(addr), __float_as_uint(v));
}

__global__ void init_m_kernel(float* __restrict__ m)
{
    int i = blockIdx.x * blockDim.x + threadIdx.x;
    if (i < NN * HH) m[i] = -INFINITY;
}

__global__ void edge_max_kernel(const int* __restrict__ src, const int* __restrict__ dst,
                                const float* __restrict__ el, const float* __restrict__ er,
                                float* __restrict__ w, float* __restrict__ m)
{
    int i = blockIdx.x * blockDim.x + threadIdx.x;
    if (i >= NE * HH) return;
    int e = i >> 2;
    int h = i & 3;
    float v = el[src[e] * HH + h] + er[dst[e] * HH + h];
    v = (v > 0.f) ? v : 0.2f * v;     // leaky_relu 0.2
    w[i] = v;
    atomicMaxF(&m[dst[e] * HH + h], v);
}

__global__ void edge_exp_kernel(const int* __restrict__ dst,
                                float* __restrict__ w,
                                const float* __restrict__ m,
                                float* __restrict__ s)
{
    int i = blockIdx.x * blockDim.x + threadIdx.x;
    if (i >= NE * HH) return;
    int e = i >> 2;
    int h = i & 3;
    int d = dst[e] * HH + h;
    float ww = expf(w[i] - m[d]);
    w[i] = ww;
    atomicAdd(&s[d], ww);
}

// ---------------------------------------------------------------------------
// Message aggregation: one warp per (edge, head); float4 gather + atomic scatter.
// ---------------------------------------------------------------------------
__global__ void edge_aggr_kernel(const int* __restrict__ src, const int* __restrict__ dst,
                                 const float* __restrict__ feat,
                                 const float* __restrict__ w, const float* __restrict__ s,
                                 float* __restrict__ out)
{
    int gw   = (blockIdx.x * blockDim.x + threadIdx.x) >> 5;
    int lane = threadIdx.x & 31;
    if (gw >= NE * HH) return;
    int e = gw >> 2;
    int h = gw & 3;
    int sn = src[e];
    int dn = dst[e];
    float a = w[gw] / s[dn * HH + h];

    float4 v = reinterpret_cast<const float4*>(feat + (size_t)sn * FF + h * DD)[lane];
    float* o = out + (size_t)dn * FF + h * DD + lane * 4;
    atomicAdd(o + 0, v.x * a);
    atomicAdd(o + 1, v.y * a);
    atomicAdd(o + 2, v.z * a);
    atomicAdd(o + 3, v.w * a);
}

// ---------------------------------------------------------------------------
// Per-type epilogue: out (+)= leaky_relu(acc + b_t), activation per type
// before the hetero sum (matches reference).
// ---------------------------------------------------------------------------
__global__ void combine_kernel(const float* __restrict__ acc, const float* __restrict__ bias,
                               float* __restrict__ out, int activate, int first)
{
    int i = blockIdx.x * blockDim.x + threadIdx.x;
    if (i >= NN * FF) return;
    int c = i & (FF - 1);
    float v = acc[i] + bias[c];
    if (activate) v = (v > 0.f) ? v : 0.01f * v;
    out[i] = first ? v : out[i] + v;
}

// ---------------------------------------------------------------------------
// Launch
// ---------------------------------------------------------------------------
extern "C" void kernel_launch(void* const* d_in, const int* in_sizes, int n_in,
                              void* d_out, int out_size)
{
    const float* x = (const float*)d_in[0];
    const int* src[2] = {(const int*)d_in[1], (const int*)d_in[3]};
    const int* dst[2] = {(const int*)d_in[2], (const int*)d_in[4]};
    const float* W [3] = {(const float*)d_in[5],  (const float*)d_in[9],  (const float*)d_in[13]};
    const float* al[3] = {(const float*)d_in[6],  (const float*)d_in[10], (const float*)d_in[14]};
    const float* ar[3] = {(const float*)d_in[7],  (const float*)d_in[11], (const float*)d_in[15]};
    const float* bb[3] = {(const float*)d_in[8],  (const float*)d_in[12], (const float*)d_in[16]};
    const float* Wout = (const float*)d_in[17];
    const float* bout = (const float*)d_in[18];
    float* out = (float*)d_out;

    float *feat, *acc, *h1, *h2, *el, *er, *m, *s, *w;
    cudaGetSymbolAddress((void**)&feat, g_feat);
    cudaGetSymbolAddress((void**)&acc,  g_acc);
    cudaGetSymbolAddress((void**)&h1,   g_h1);
    cudaGetSymbolAddress((void**)&h2,   g_h2);
    cudaGetSymbolAddress((void**)&el,   g_el);
    cudaGetSymbolAddress((void**)&er,   g_er);
    cudaGetSymbolAddress((void**)&m,    g_m);
    cudaGetSymbolAddress((void**)&s,    g_s);
    cudaGetSymbolAddress((void**)&w,    g_w);

    const int nhThreads = NN * HH;                    // 160000
    const int ehThreads = NE * HH;                    // 600000
    const int nhBlocks  = (nhThreads + 255) / 256;
    const int ehBlocks  = (ehThreads + 255) / 256;
    const int lgBlocks  = (nhThreads * 32 + 255) / 256;   // warp per (n,h)
    const int agBlocks  = (ehThreads + 7) / 8;            // warp per (e,h), 8 warps/block
    const int cbBlocks  = ((size_t)NN * FF + 255) / 256;

    const float* hin = x;
    float* houts[3] = {h1, h2, h1};
    const int Ks[3] = {1024, 512, 512};

    const int gy = (NN + BM - 1) / BM;                // 313

    for (int L = 0; L < 3; L++) {
        float* hout = houts[L];
        for (int t = 0; t < 2; t++) {
            const float* Wt = W[L] + (size_t)t * Ks[L] * FF;
            dim3 grid(FF / BN, gy);
            gemm_tf32<false><<<grid, 256>>>(hin, Wt, feat, NN, FF, Ks[L], nullptr);

            logits_kernel<<<lgBlocks, 256>>>(feat, al[L] + t * FF, ar[L] + t * FF, el, er);

            init_m_kernel<<<nhBlocks, 256>>>(m);
            cudaMemsetAsync(s, 0, (size_t)NN * HH * sizeof(float), 0);

            edge_max_kernel<<<ehBlocks, 256>>>(src[t], dst[t], el, er, w, m);
            edge_exp_kernel<<<ehBlocks, 256>>>(dst[t], w, m, s);

            cudaMemsetAsync(acc, 0, (size_t)NN * FF * sizeof(float), 0);
            edge_aggr_kernel<<<agBlocks, 256>>>(src[t], dst[t], feat, w, s, acc);

            combine_kernel<<<cbBlocks, 256>>>(acc, bb[L] + t * FF, hout,
                                              (L < 2) ? 1 : 0, (t == 0) ? 1 : 0);
        }
        hin = hout;
    }

    dim3 gridF((NOUT + BN - 1) / BN, gy);
    gemm_tf32<true><<<gridF, 256>>>(hin, Wout, out, NN, NOUT, FF, bout);
}

// round 4
// speedup vs baseline: 2.8971x; 1.2902x over previous
#include <cuda_runtime.h>
#include <math.h>
#include <stdint.h>

// Problem constants (fixed-shape problem)
#define NN 40000      // nodes
#define NE 150000     // edges per type
#define HH 4          // heads
#define DD 128        // per-head dim
#define FF 512        // HH*DD
#define NOUT 2983

// ---------------------------------------------------------------------------
// Scratch (device globals; no allocation allowed)
// ---------------------------------------------------------------------------
__device__ float g_feat[(size_t)NN * FF];
__device__ float g_h1  [(size_t)NN * FF];
__device__ float g_h2  [(size_t)NN * FF];
__device__ float g_el  [NN * HH];
__device__ float g_er  [NN * HH];
__device__ int   g_deg [NN];
__device__ int   g_cur [NN];
__device__ int   g_rp  [2][NN + 1];
__device__ int   g_csrc[2][NE];

// ---------------------------------------------------------------------------
// TF32 tensor-core GEMM: C[M,N] = A[M,K] @ B[K,N] (row-major), optional bias.
// BM=128, BN=128, BK=16, 256 threads (8 warps), warp tile 64x32,
// mma.sync.aligned.m16n8k8.row.col.f32.tf32.tf32.f32.
// ---------------------------------------------------------------------------
#define BM 128
#define BN 128
#define BK 16
#define AS_LD 20
#define BS_LD 132

__device__ __forceinline__ float to_tf32(float x)
{
    unsigned r;
    asm("cvt.rna.tf32.f32 %0, %1;" : "=r"(r) : "f"(x));
    return __uint_as_float(r);
}

__device__ __forceinline__ void mma_tf32(float c[4],
                                         float a0, float a1, float a2, float a3,
                                         float b0, float b1)
{
    asm volatile(
        "mma.sync.aligned.m16n8k8.row.col.f32.tf32.tf32.f32 "
        "{%0,%1,%2,%3}, {%4,%5,%6,%7}, {%8,%9}, {%0,%1,%2,%3};\n"
        : "+f"(c[0]), "+f"(c[1]), "+f"(c[2]), "+f"(c[3])
        : "r"(__float_as_uint(a0)), "r"(__float_as_uint(a1)),
          "r"(__float_as_uint(a2)), "r"(__float_as_uint(a3)),
          "r"(__float_as_uint(b0)), "r"(__float_as_uint(b1)));
}

template <bool ADD_BIAS>
__global__ __launch_bounds__(256)
void gemm_tf32(const float* __restrict__ A, const float* __restrict__ B,
               float* __restrict__ C, int M, int N, int K,
               const float* __restrict__ bias)
{
    __shared__ float As[2][BM][AS_LD];
    __shared__ float Bs[2][BK][BS_LD];

    const int tid  = threadIdx.x;
    const int wid  = tid >> 5;
    const int lane = tid & 31;
    const int wm   = wid & 1;
    const int wn   = wid >> 1;
    const int g    = lane >> 2;
    const int q    = lane & 3;

    const int bm = blockIdx.y * BM;
    const int bn = blockIdx.x * BN;

    float c[4][4][4];
    #pragma unroll
    for (int i = 0; i < 4; i++)
        #pragma unroll
        for (int j = 0; j < 4; j++)
            #pragma unroll
            for (int r = 0; r < 4; r++) c[i][j][r] = 0.f;

    const int af0 = tid * 2;
    const int bc  = tid & 127;
    const int br0 = (tid >> 7) * 8;

    float4 aReg[2];
    float  bReg[8];

    const int nt = K / BK;

    {
        #pragma unroll
        for (int i = 0; i < 2; i++) {
            int f   = af0 + i;
            int row = f >> 2;
            int kc  = (f & 3) * 4;
            int m   = bm + row;
            aReg[i] = make_float4(0.f, 0.f, 0.f, 0.f);
            if (m < M)
                aReg[i] = *reinterpret_cast<const float4*>(A + (size_t)m * K + kc);
        }
        int n = bn + bc;
        #pragma unroll
        for (int j = 0; j < 8; j++)
            bReg[j] = (n < N) ? B[(size_t)(br0 + j) * N + n] : 0.f;

        #pragma unroll
        for (int i = 0; i < 2; i++) {
            int f   = af0 + i;
            int row = f >> 2;
            int kc  = (f & 3) * 4;
            As[0][row][kc + 0] = to_tf32(aReg[i].x);
            As[0][row][kc + 1] = to_tf32(aReg[i].y);
            As[0][row][kc + 2] = to_tf32(aReg[i].z);
            As[0][row][kc + 3] = to_tf32(aReg[i].w);
        }
        #pragma unroll
        for (int j = 0; j < 8; j++)
            Bs[0][br0 + j][bc] = to_tf32(bReg[j]);
    }
    __syncthreads();

    for (int t = 0; t < nt; t++) {
        const int cur = t & 1;
        const int nxt = cur ^ 1;
        const bool havenext = (t + 1 < nt);

        if (havenext) {
            int k0 = (t + 1) * BK;
            #pragma unroll
            for (int i = 0; i < 2; i++) {
                int f   = af0 + i;
                int row = f >> 2;
                int kc  = (f & 3) * 4;
                int m   = bm + row;
                aReg[i] = make_float4(0.f, 0.f, 0.f, 0.f);
                if (m < M)
                    aReg[i] = *reinterpret_cast<const float4*>(A + (size_t)m * K + k0 + kc);
            }
            int n = bn + bc;
            #pragma unroll
            for (int j = 0; j < 8; j++)
                bReg[j] = (n < N) ? B[(size_t)(k0 + br0 + j) * N + n] : 0.f;
        }

        #pragma unroll
        for (int ks = 0; ks < 2; ks++) {
            const int kb = ks * 8;
            float a[4][4], b[4][2];
            #pragma unroll
            for (int mi = 0; mi < 4; mi++) {
                int r = wm * 64 + mi * 16 + g;
                a[mi][0] = As[cur][r    ][kb + q];
                a[mi][1] = As[cur][r + 8][kb + q];
                a[mi][2] = As[cur][r    ][kb + q + 4];
                a[mi][3] = As[cur][r + 8][kb + q + 4];
            }
            #pragma unroll
            for (int nj = 0; nj < 4; nj++) {
                int cn = wn * 32 + nj * 8 + g;
                b[nj][0] = Bs[cur][kb + q    ][cn];
                b[nj][1] = Bs[cur][kb + q + 4][cn];
            }
            #pragma unroll
            for (int mi = 0; mi < 4; mi++)
                #pragma unroll
                for (int nj = 0; nj < 4; nj++)
                    mma_tf32(c[mi][nj], a[mi][0], a[mi][1], a[mi][2], a[mi][3],
                             b[nj][0], b[nj][1]);
        }

        if (havenext) {
            #pragma unroll
            for (int i = 0; i < 2; i++) {
                int f   = af0 + i;
                int row = f >> 2;
                int kc  = (f & 3) * 4;
                As[nxt][row][kc + 0] = to_tf32(aReg[i].x);
                As[nxt][row][kc + 1] = to_tf32(aReg[i].y);
                As[nxt][row][kc + 2] = to_tf32(aReg[i].z);
                As[nxt][row][kc + 3] = to_tf32(aReg[i].w);
            }
            #pragma unroll
            for (int j = 0; j < 8; j++)
                Bs[nxt][br0 + j][bc] = to_tf32(bReg[j]);
        }
        __syncthreads();
    }

    #pragma unroll
    for (int mi = 0; mi < 4; mi++) {
        int row0 = bm + wm * 64 + mi * 16 + g;
        #pragma unroll
        for (int nj = 0; nj < 4; nj++) {
            int col0 = bn + wn * 32 + nj * 8 + 2 * q;
            #pragma unroll
            for (int r = 0; r < 4; r++) {
                int row = row0 + (r >= 2 ? 8 : 0);
                int col = col0 + (r & 1);
                if (row < M && col < N) {
                    float v = c[mi][nj][r];
                    if (ADD_BIAS) v += bias[col];
                    C[(size_t)row * N + col] = v;
                }
            }
        }
    }
}

// ---------------------------------------------------------------------------
// CSR construction (per edge type, built once per launch, reused 3 layers)
// ---------------------------------------------------------------------------
__global__ void hist_kernel(const int* __restrict__ dst, int* __restrict__ deg)
{
    int i = blockIdx.x * blockDim.x + threadIdx.x;
    if (i < NE) atomicAdd(&deg[dst[i]], 1);
}

// Exclusive scan of deg[NN] -> rp[NN+1]; also copies starts into cur.
// Single block, 1024 threads, 40 elements per thread.
__global__ __launch_bounds__(1024)
void scan_kernel(const int* __restrict__ deg, int* __restrict__ rp,
                 int* __restrict__ cur)
{
    const int CH = 40;              // 1024*40 >= 40000
    __shared__ int sm[1024];
    int tid = threadIdx.x;
    int start = tid * CH;

    int sum = 0;
    #pragma unroll 4
    for (int j = 0; j < CH; j++) {
        int i = start + j;
        if (i < NN) sum += deg[i];
    }
    sm[tid] = sum;
    __syncthreads();
    for (int off = 1; off < 1024; off <<= 1) {
        int t = (tid >= off) ? sm[tid - off] : 0;
        __syncthreads();
        sm[tid] += t;
        __syncthreads();
    }
    int run = sm[tid] - sum;        // exclusive prefix
    for (int j = 0; j < CH; j++) {
        int i = start + j;
        if (i < NN) {
            rp[i]  = run;
            cur[i] = run;
            run += deg[i];
        }
    }
    if (tid == 1023) rp[NN] = sm[1023];
}

__global__ void scatter_kernel(const int* __restrict__ src, const int* __restrict__ dst,
                               int* __restrict__ cur, int* __restrict__ csrc)
{
    int i = blockIdx.x * blockDim.x + threadIdx.x;
    if (i < NE) {
        int p = atomicAdd(&cur[dst[i]], 1);
        csrc[p] = src[i];
    }
}

// ---------------------------------------------------------------------------
// Attention logits: el[n,h] = <feat[n,h,:], al[h,:]>, er likewise.
// One warp per (node, head).
// ---------------------------------------------------------------------------
__global__ void logits_kernel(const float* __restrict__ feat,
                              const float* __restrict__ al,
                              const float* __restrict__ ar,
                              float* __restrict__ el, float* __restrict__ er)
{
    int gw   = (blockIdx.x * blockDim.x + threadIdx.x) >> 5;
    int lane = threadIdx.x & 31;
    if (gw >= NN * HH) return;
    int n = gw >> 2;
    int h = gw & 3;

    float4 fv = reinterpret_cast<const float4*>(feat + (size_t)n * FF + h * DD)[lane];
    float4 av = reinterpret_cast<const float4*>(al + h * DD)[lane];
    float4 rv = reinterpret_cast<const float4*>(ar + h * DD)[lane];

    float dl = fv.x * av.x + fv.y * av.y + fv.z * av.z + fv.w * av.w;
    float dr = fv.x * rv.x + fv.y * rv.y + fv.z * rv.z + fv.w * rv.w;
    #pragma unroll
    for (int o = 16; o; o >>= 1) {
        dl += __shfl_xor_sync(0xFFFFFFFFu, dl, o);
        dr += __shfl_xor_sync(0xFFFFFFFFu, dr, o);
    }
    if (lane == 0) { el[gw] = dl; er[gw] = dr; }
}

// ---------------------------------------------------------------------------
// Fused segment-softmax + gather-aggregate + bias + activation + hetero-sum.
// One warp per (dst node, head). No atomics, no scratch passes.
//   hout[n,h,:] (+)= act( sum_e a_e * feat[src_e,h,:] + bias[h,:] )
// ---------------------------------------------------------------------------
__global__ __launch_bounds__(256)
void aggr_fused_kernel(const int* __restrict__ rp, const int* __restrict__ csrc,
                       const float* __restrict__ el, const float* __restrict__ er,
                       const float* __restrict__ feat, const float* __restrict__ bias,
                       float* __restrict__ hout, int activate, int first)
{
    int gw   = (blockIdx.x * blockDim.x + threadIdx.x) >> 5;
    int lane = threadIdx.x & 31;
    if (gw >= NN * HH) return;
    int n = gw >> 2;
    int h = gw & 3;

    int beg = rp[n];
    int end = rp[n + 1];
    float erd = er[gw];

    // segment max
    float mx = -INFINITY;
    for (int i = beg + lane; i < end; i += 32) {
        int s = csrc[i];
        float v = el[s * HH + h] + erd;
        v = (v > 0.f) ? v : 0.2f * v;
        mx = fmaxf(mx, v);
    }
    #pragma unroll
    for (int o = 16; o; o >>= 1)
        mx = fmaxf(mx, __shfl_xor_sync(0xFFFFFFFFu, mx, o));

    // segment sum of exp
    float ss = 0.f;
    for (int i = beg + lane; i < end; i += 32) {
        int s = csrc[i];
        float v = el[s * HH + h] + erd;
        v = (v > 0.f) ? v : 0.2f * v;
        ss += __expf(v - mx);
    }
    #pragma unroll
    for (int o = 16; o; o >>= 1)
        ss += __shfl_xor_sync(0xFFFFFFFFu, ss, o);
    float inv = (end > beg) ? 1.f / ss : 0.f;

    // weighted gather-accumulate (serial over segment; deg avg ~3.75)
    float4 acc = make_float4(0.f, 0.f, 0.f, 0.f);
    for (int i = beg; i < end; i++) {
        int s = csrc[i];                               // broadcast load
        float v = el[s * HH + h] + erd;
        v = (v > 0.f) ? v : 0.2f * v;
        float a = __expf(v - mx) * inv;
        float4 fv = reinterpret_cast<const float4*>(feat + (size_t)s * FF + h * DD)[lane];
        acc.x = fmaf(a, fv.x, acc.x);
        acc.y = fmaf(a, fv.y, acc.y);
        acc.z = fmaf(a, fv.z, acc.z);
        acc.w = fmaf(a, fv.w, acc.w);
    }

    // epilogue: bias, per-type activation, hetero sum
    float4 b4 = reinterpret_cast<const float4*>(bias + h * DD)[lane];
    float4 o4;
    o4.x = acc.x + b4.x; o4.y = acc.y + b4.y;
    o4.z = acc.z + b4.z; o4.w = acc.w + b4.w;
    if (activate) {
        o4.x = (o4.x > 0.f) ? o4.x : 0.01f * o4.x;
        o4.y = (o4.y > 0.f) ? o4.y : 0.01f * o4.y;
        o4.z = (o4.z > 0.f) ? o4.z : 0.01f * o4.z;
        o4.w = (o4.w > 0.f) ? o4.w : 0.01f * o4.w;
    }
    float4* op = reinterpret_cast<float4*>(hout + (size_t)n * FF + h * DD) + lane;
    if (first) {
        *op = o4;
    } else {
        float4 cu = *op;
        cu.x += o4.x; cu.y += o4.y; cu.z += o4.z; cu.w += o4.w;
        *op = cu;
    }
}

// ---------------------------------------------------------------------------
// Launch
// ---------------------------------------------------------------------------
extern "C" void kernel_launch(void* const* d_in, const int* in_sizes, int n_in,
                              void* d_out, int out_size)
{
    const float* x = (const float*)d_in[0];
    const int* src[2] = {(const int*)d_in[1], (const int*)d_in[3]};
    const int* dst[2] = {(const int*)d_in[2], (const int*)d_in[4]};
    const float* W [3] = {(const float*)d_in[5],  (const float*)d_in[9],  (const float*)d_in[13]};
    const float* al[3] = {(const float*)d_in[6],  (const float*)d_in[10], (const float*)d_in[14]};
    const float* ar[3] = {(const float*)d_in[7],  (const float*)d_in[11], (const float*)d_in[15]};
    const float* bb[3] = {(const float*)d_in[8],  (const float*)d_in[12], (const float*)d_in[16]};
    const float* Wout = (const float*)d_in[17];
    const float* bout = (const float*)d_in[18];
    float* out = (float*)d_out;

    float *feat, *h1, *h2, *el, *er;
    int *deg, *cur, *rp, *csrc;
    cudaGetSymbolAddress((void**)&feat, g_feat);
    cudaGetSymbolAddress((void**)&h1,   g_h1);
    cudaGetSymbolAddress((void**)&h2,   g_h2);
    cudaGetSymbolAddress((void**)&el,   g_el);
    cudaGetSymbolAddress((void**)&er,   g_er);
    cudaGetSymbolAddress((void**)&deg,  g_deg);
    cudaGetSymbolAddress((void**)&cur,  g_cur);
    cudaGetSymbolAddress((void**)&rp,   g_rp);
    cudaGetSymbolAddress((void**)&csrc, g_csrc);

    const int neBlocks = (NE + 255) / 256;
    const int lgBlocks = (NN * HH * 32 + 255) / 256;   // warp per (n,h)
    const int agBlocks = (NN * HH + 7) / 8;            // warp per (n,h), 8 warps/block

    // ---- Build CSR for both edge types (reused across the 3 layers) ----
    for (int t = 0; t < 2; t++) {
        int* rpt = rp + t * (NN + 1);
        int* cst = csrc + t * NE;
        cudaMemsetAsync(deg, 0, NN * sizeof(int), 0);
        hist_kernel<<<neBlocks, 256>>>(dst[t], deg);
        scan_kernel<<<1, 1024>>>(deg, rpt, cur);
        scatter_kernel<<<neBlocks, 256>>>(src[t], dst[t], cur, cst);
    }

    const float* hin = x;
    float* houts[3] = {h1, h2, h1};
    const int Ks[3] = {1024, 512, 512};

    const int gy = (NN + BM - 1) / BM;

    for (int L = 0; L < 3; L++) {
        float* hout = houts[L];
        for (int t = 0; t < 2; t++) {
            const float* Wt = W[L] + (size_t)t * Ks[L] * FF;
            dim3 grid(FF / BN, gy);
            gemm_tf32<false><<<grid, 256>>>(hin, Wt, feat, NN, FF, Ks[L], nullptr);

            logits_kernel<<<lgBlocks, 256>>>(feat, al[L] + t * FF, ar[L] + t * FF, el, er);

            aggr_fused_kernel<<<agBlocks, 256>>>(rp + t * (NN + 1), csrc + t * NE,
                                                 el, er, feat, bb[L] + t * FF, hout,
                                                 (L < 2) ? 1 : 0, (t == 0) ? 1 : 0);
        }
        hin = hout;
    }

    dim3 gridF((NOUT + BN - 1) / BN, gy);
    gemm_tf32<true><<<gridF, 256>>>(hin, Wout, out, NN, NOUT, FF, bout);
}

// round 5
// speedup vs baseline: 3.4109x; 1.1773x over previous
#include <cuda_runtime.h>
#include <math.h>
#include <stdint.h>

// Problem constants (fixed-shape problem)
#define NN 40000      // nodes
#define NE 150000     // edges per type
#define HH 4          // heads
#define DD 128        // per-head dim
#define FF 512        // HH*DD
#define NOUT 2983
#define NOUTP 2984    // padded (16B-aligned rows for cp.async)

// ---------------------------------------------------------------------------
// Scratch (device globals; no allocation allowed)
// ---------------------------------------------------------------------------
__device__ float g_feat[(size_t)NN * FF];
__device__ float g_h1  [(size_t)NN * FF];
__device__ float g_h2  [(size_t)NN * FF];
__device__ float g_xc  [(size_t)NN * 1024];          // tf32-rounded x
__device__ float g_w0  [2 * 1024 * FF];              // tf32-rounded W0
__device__ float g_w1  [2 * FF * FF];
__device__ float g_w2  [2 * FF * FF];
__device__ float g_wo  [FF * NOUTP];                 // tf32-rounded, padded Wout
__device__ float g_el  [NN * HH];
__device__ float g_er  [NN * HH];
__device__ int   g_deg [NN];
__device__ int   g_cur [NN];
__device__ int   g_rp  [2][NN + 1];
__device__ int   g_csrc[2][NE];

// ---------------------------------------------------------------------------
// Helpers
// ---------------------------------------------------------------------------
__device__ __forceinline__ float to_tf32(float x)
{
    unsigned r;
    asm("cvt.rna.tf32.f32 %0, %1;" : "=r"(r) : "f"(x));
    return __uint_as_float(r);
}

__device__ __forceinline__ void mma_tf32(float c[4],
                                         float a0, float a1, float a2, float a3,
                                         float b0, float b1)
{
    asm volatile(
        "mma.sync.aligned.m16n8k8.row.col.f32.tf32.tf32.f32 "
        "{%0,%1,%2,%3}, {%4,%5,%6,%7}, {%8,%9}, {%0,%1,%2,%3};\n"
        : "+f"(c[0]), "+f"(c[1]), "+f"(c[2]), "+f"(c[3])
        : "r"(__float_as_uint(a0)), "r"(__float_as_uint(a1)),
          "r"(__float_as_uint(a2)), "r"(__float_as_uint(a3)),
          "r"(__float_as_uint(b0)), "r"(__float_as_uint(b1)));
}

__device__ __forceinline__ void cp_async16(uint32_t saddr, const void* gptr, int bytes)
{
    asm volatile("cp.async.cg.shared.global [%0], [%1], 16, %2;\n"
                 :: "r"(saddr), "l"(gptr), "r"(bytes));
}
__device__ __forceinline__ void cp_commit()
{
    asm volatile("cp.async.commit_group;\n");
}
__device__ __forceinline__ void cp_wait2()
{
    asm volatile("cp.async.wait_group 2;\n");
}

// ---------------------------------------------------------------------------
// TF32 tensor-core GEMM, cp.async 4-stage pipeline.
// C[M,Ncols] = A[M,K] @ B[K,NB] (row-major), Ncols <= NB.
// Inputs A,B must be PRE-ROUNDED to tf32. BM=BN=128, BK=16, 256 thr, 8 warps.
// ---------------------------------------------------------------------------
#define BM 128
#define BN 128
#define BK 16
#define STAGES 4
#define AS_LD 24
#define BS_LD 136
#define A_FLOATS (BM * AS_LD)                 // 3072
#define STG_FLOATS (A_FLOATS + BK * BS_LD)    // 3072 + 2176 = 5248
#define SMEM_BYTES (STAGES * STG_FLOATS * 4)  // 83968

extern __shared__ float smem_dyn[];

template <bool ADD_BIAS>
__global__ __launch_bounds__(256)
void gemm_pipe(const float* __restrict__ A, const float* __restrict__ B,
               float* __restrict__ C, int M, int Ncols, int NB, int K,
               const float* __restrict__ bias)
{
    const int tid  = threadIdx.x;
    const int wid  = tid >> 5;
    const int lane = tid & 31;
    const int wm   = wid & 1;
    const int wn   = wid >> 1;
    const int g    = lane >> 2;
    const int q    = lane & 3;

    const int bm = blockIdx.y * BM;
    const int bn = blockIdx.x * BN;

    const uint32_t sbase = (uint32_t)__cvta_generic_to_shared(smem_dyn);

    float c[4][4][4];
    #pragma unroll
    for (int i = 0; i < 4; i++)
        #pragma unroll
        for (int j = 0; j < 4; j++)
            #pragma unroll
            for (int r = 0; r < 4; r++) c[i][j][r] = 0.f;

    // per-thread load mapping (2 x 16B chunks for A, 2 for B)
    const int aRow0 = (tid * 2) >> 2;          // chunk f=tid*2+i: row=f>>2
    const int bRow0 = (tid * 2) >> 5;          // row = f>>5

    const int nt = K / BK;

    auto load_stage = [&](int s, int t) {
        const int k0 = t * BK;
        const uint32_t ss = sbase + (uint32_t)(s * STG_FLOATS) * 4u;
        #pragma unroll
        for (int i = 0; i < 2; i++) {
            int f   = tid * 2 + i;
            int row = f >> 2;
            int kc  = (f & 3) * 4;
            int m   = bm + row;
            const float* ga = (m < M) ? (A + (size_t)m * K + k0 + kc) : A;
            cp_async16(ss + (uint32_t)(row * AS_LD + kc) * 4u, ga, (m < M) ? 16 : 0);
        }
        #pragma unroll
        for (int i = 0; i < 2; i++) {
            int f    = tid * 2 + i;
            int brow = f >> 5;
            int bcol = (f & 31) * 4;
            int n    = bn + bcol;
            int rem  = NB - n;
            int bytes = rem >= 4 ? 16 : (rem > 0 ? rem * 4 : 0);
            const float* gb = (bytes > 0) ? (B + (size_t)(k0 + brow) * NB + n) : B;
            cp_async16(ss + (uint32_t)(A_FLOATS + brow * BS_LD + bcol) * 4u, gb, bytes);
        }
        cp_commit();
    };

    // prologue: stages 0..2
    #pragma unroll
    for (int s = 0; s < STAGES - 1; s++)
        load_stage(s, s);

    for (int t = 0; t < nt; t++) {
        cp_wait2();
        __syncthreads();

        const float* As = smem_dyn + (t & 3) * STG_FLOATS;
        const float* Bs = As + A_FLOATS;

        #pragma unroll
        for (int ks = 0; ks < 2; ks++) {
            const int kb = ks * 8;
            float a[4][4], b[4][2];
            #pragma unroll
            for (int mi = 0; mi < 4; mi++) {
                int r = wm * 64 + mi * 16 + g;
                a[mi][0] = As[(r    ) * AS_LD + kb + q];
                a[mi][1] = As[(r + 8) * AS_LD + kb + q];
                a[mi][2] = As[(r    ) * AS_LD + kb + q + 4];
                a[mi][3] = As[(r + 8) * AS_LD + kb + q + 4];
            }
            #pragma unroll
            for (int nj = 0; nj < 4; nj++) {
                int cn = wn * 32 + nj * 8 + g;
                b[nj][0] = Bs[(kb + q    ) * BS_LD + cn];
                b[nj][1] = Bs[(kb + q + 4) * BS_LD + cn];
            }
            #pragma unroll
            for (int mi = 0; mi < 4; mi++)
                #pragma unroll
                for (int nj = 0; nj < 4; nj++)
                    mma_tf32(c[mi][nj], a[mi][0], a[mi][1], a[mi][2], a[mi][3],
                             b[nj][0], b[nj][1]);
        }

        if (t + STAGES - 1 < nt)
            load_stage((t + STAGES - 1) & 3, t + STAGES - 1);
        else
            cp_commit();   // keep group count consistent
    }

    // epilogue
    #pragma unroll
    for (int mi = 0; mi < 4; mi++) {
        int row0 = bm + wm * 64 + mi * 16 + g;
        #pragma unroll
        for (int nj = 0; nj < 4; nj++) {
            int col0 = bn + wn * 32 + nj * 8 + 2 * q;
            #pragma unroll
            for (int r = 0; r < 4; r++) {
                int row = row0 + (r >= 2 ? 8 : 0);
                int col = col0 + (r & 1);
                if (row < M && col < Ncols) {
                    float v = c[mi][nj][r];
                    if (ADD_BIAS) v += bias[col];
                    C[(size_t)row * Ncols + col] = v;
                }
            }
        }
    }
}

// ---------------------------------------------------------------------------
// tf32 pre-rounding converts
// ---------------------------------------------------------------------------
__global__ void cvt_kernel(const float* __restrict__ in, float* __restrict__ out, int n4)
{
    int i = blockIdx.x * blockDim.x + threadIdx.x;
    if (i >= n4) return;
    float4 v = reinterpret_cast<const float4*>(in)[i];
    v.x = to_tf32(v.x); v.y = to_tf32(v.y);
    v.z = to_tf32(v.z); v.w = to_tf32(v.w);
    reinterpret_cast<float4*>(out)[i] = v;
}

__global__ void pad_wout_kernel(const float* __restrict__ w, float* __restrict__ o)
{
    int i = blockIdx.x * blockDim.x + threadIdx.x;
    if (i >= FF * NOUTP) return;
    int r = i / NOUTP, c = i - r * NOUTP;
    o[i] = (c < NOUT) ? to_tf32(w[r * NOUT + c]) : 0.f;
}

// ---------------------------------------------------------------------------
// CSR construction
// ---------------------------------------------------------------------------
__global__ void hist_kernel(const int* __restrict__ dst, int* __restrict__ deg)
{
    int i = blockIdx.x * blockDim.x + threadIdx.x;
    if (i < NE) atomicAdd(&deg[dst[i]], 1);
}

__global__ __launch_bounds__(1024)
void scan_kernel(const int* __restrict__ deg, int* __restrict__ rp,
                 int* __restrict__ cur)
{
    const int CH = 40;
    __shared__ int sm[1024];
    int tid = threadIdx.x;
    int start = tid * CH;

    int sum = 0;
    #pragma unroll 4
    for (int j = 0; j < CH; j++) {
        int i = start + j;
        if (i < NN) sum += deg[i];
    }
    sm[tid] = sum;
    __syncthreads();
    for (int off = 1; off < 1024; off <<= 1) {
        int t = (tid >= off) ? sm[tid - off] : 0;
        __syncthreads();
        sm[tid] += t;
        __syncthreads();
    }
    int run = sm[tid] - sum;
    for (int j = 0; j < CH; j++) {
        int i = start + j;
        if (i < NN) {
            rp[i]  = run;
            cur[i] = run;
            run += deg[i];
        }
    }
    if (tid == 1023) rp[NN] = sm[1023];
}

__global__ void scatter_kernel(const int* __restrict__ src, const int* __restrict__ dst,
                               int* __restrict__ cur, int* __restrict__ csrc)
{
    int i = blockIdx.x * blockDim.x + threadIdx.x;
    if (i < NE) {
        int p = atomicAdd(&cur[dst[i]], 1);
        csrc[p] = src[i];
    }
}

// ---------------------------------------------------------------------------
// Attention logits: one warp per (node, head)
// ---------------------------------------------------------------------------
__global__ void logits_kernel(const float* __restrict__ feat,
                              const float* __restrict__ al,
                              const float* __restrict__ ar,
                              float* __restrict__ el, float* __restrict__ er)
{
    int gw   = (blockIdx.x * blockDim.x + threadIdx.x) >> 5;
    int lane = threadIdx.x & 31;
    if (gw >= NN * HH) return;
    int n = gw >> 2;
    int h = gw & 3;

    float4 fv = reinterpret_cast<const float4*>(feat + (size_t)n * FF + h * DD)[lane];
    float4 av = reinterpret_cast<const float4*>(al + h * DD)[lane];
    float4 rv = reinterpret_cast<const float4*>(ar + h * DD)[lane];

    float dl = fv.x * av.x + fv.y * av.y + fv.z * av.z + fv.w * av.w;
    float dr = fv.x * rv.x + fv.y * rv.y + fv.z * rv.z + fv.w * rv.w;
    #pragma unroll
    for (int o = 16; o; o >>= 1) {
        dl += __shfl_xor_sync(0xFFFFFFFFu, dl, o);
        dr += __shfl_xor_sync(0xFFFFFFFFu, dr, o);
    }
    if (lane == 0) { el[gw] = dl; er[gw] = dr; }
}

// ---------------------------------------------------------------------------
// Fused segment-softmax + gather-aggregate + bias + activation + hetero-sum.
// Output is written PRE-ROUNDED to tf32 (consumed only by the next GEMM).
// ---------------------------------------------------------------------------
__global__ __launch_bounds__(256)
void aggr_fused_kernel(const int* __restrict__ rp, const int* __restrict__ csrc,
                       const float* __restrict__ el, const float* __restrict__ er,
                       const float* __restrict__ feat, const float* __restrict__ bias,
                       float* __restrict__ hout, int activate, int first)
{
    int gw   = (blockIdx.x * blockDim.x + threadIdx.x) >> 5;
    int lane = threadIdx.x & 31;
    if (gw >= NN * HH) return;
    int n = gw >> 2;
    int h = gw & 3;

    int beg = rp[n];
    int end = rp[n + 1];
    float erd = er[gw];

    float mx = -INFINITY;
    for (int i = beg + lane; i < end; i += 32) {
        int s = csrc[i];
        float v = el[s * HH + h] + erd;
        v = (v > 0.f) ? v : 0.2f * v;
        mx = fmaxf(mx, v);
    }
    #pragma unroll
    for (int o = 16; o; o >>= 1)
        mx = fmaxf(mx, __shfl_xor_sync(0xFFFFFFFFu, mx, o));

    float ss = 0.f;
    for (int i = beg + lane; i < end; i += 32) {
        int s = csrc[i];
        float v = el[s * HH + h] + erd;
        v = (v > 0.f) ? v : 0.2f * v;
        ss += __expf(v - mx);
    }
    #pragma unroll
    for (int o = 16; o; o >>= 1)
        ss += __shfl_xor_sync(0xFFFFFFFFu, ss, o);
    float inv = (end > beg) ? 1.f / ss : 0.f;

    float4 acc = make_float4(0.f, 0.f, 0.f, 0.f);
    for (int i = beg; i < end; i++) {
        int s = csrc[i];
        float v = el[s * HH + h] + erd;
        v = (v > 0.f) ? v : 0.2f * v;
        float a = __expf(v - mx) * inv;
        float4 fv = reinterpret_cast<const float4*>(feat + (size_t)s * FF + h * DD)[lane];
        acc.x = fmaf(a, fv.x, acc.x);
        acc.y = fmaf(a, fv.y, acc.y);
        acc.z = fmaf(a, fv.z, acc.z);
        acc.w = fmaf(a, fv.w, acc.w);
    }

    float4 b4 = reinterpret_cast<const float4*>(bias + h * DD)[lane];
    float4 o4;
    o4.x = acc.x + b4.x; o4.y = acc.y + b4.y;
    o4.z = acc.z + b4.z; o4.w = acc.w + b4.w;
    if (activate) {
        o4.x = (o4.x > 0.f) ? o4.x : 0.01f * o4.x;
        o4.y = (o4.y > 0.f) ? o4.y : 0.01f * o4.y;
        o4.z = (o4.z > 0.f) ? o4.z : 0.01f * o4.z;
        o4.w = (o4.w > 0.f) ? o4.w : 0.01f * o4.w;
    }
    float4* op = reinterpret_cast<float4*>(hout + (size_t)n * FF + h * DD) + lane;
    if (first) {
        o4.x = to_tf32(o4.x); o4.y = to_tf32(o4.y);
        o4.z = to_tf32(o4.z); o4.w = to_tf32(o4.w);
        *op = o4;
    } else {
        float4 cu = *op;
        o4.x = to_tf32(cu.x + o4.x); o4.y = to_tf32(cu.y + o4.y);
        o4.z = to_tf32(cu.z + o4.z); o4.w = to_tf32(cu.w + o4.w);
        *op = o4;
    }
}

// ---------------------------------------------------------------------------
// Launch
// ---------------------------------------------------------------------------
extern "C" void kernel_launch(void* const* d_in, const int* in_sizes, int n_in,
                              void* d_out, int out_size)
{
    const float* x = (const float*)d_in[0];
    const int* src[2] = {(const int*)d_in[1], (const int*)d_in[3]};
    const int* dst[2] = {(const int*)d_in[2], (const int*)d_in[4]};
    const float* W [3] = {(const float*)d_in[5],  (const float*)d_in[9],  (const float*)d_in[13]};
    const float* al[3] = {(const float*)d_in[6],  (const float*)d_in[10], (const float*)d_in[14]};
    const float* ar[3] = {(const float*)d_in[7],  (const float*)d_in[11], (const float*)d_in[15]};
    const float* bb[3] = {(const float*)d_in[8],  (const float*)d_in[12], (const float*)d_in[16]};
    const float* Wout = (const float*)d_in[17];
    const float* bout = (const float*)d_in[18];
    float* out = (float*)d_out;

    float *feat, *h1, *h2, *xc, *w0c, *w1c, *w2c, *woc, *el, *er;
    int *deg, *cur, *rp, *csrc;
    cudaGetSymbolAddress((void**)&feat, g_feat);
    cudaGetSymbolAddress((void**)&h1,   g_h1);
    cudaGetSymbolAddress((void**)&h2,   g_h2);
    cudaGetSymbolAddress((void**)&xc,   g_xc);
    cudaGetSymbolAddress((void**)&w0c,  g_w0);
    cudaGetSymbolAddress((void**)&w1c,  g_w1);
    cudaGetSymbolAddress((void**)&w2c,  g_w2);
    cudaGetSymbolAddress((void**)&woc,  g_wo);
    cudaGetSymbolAddress((void**)&el,   g_el);
    cudaGetSymbolAddress((void**)&er,   g_er);
    cudaGetSymbolAddress((void**)&deg,  g_deg);
    cudaGetSymbolAddress((void**)&cur,  g_cur);
    cudaGetSymbolAddress((void**)&rp,   g_rp);
    cudaGetSymbolAddress((void**)&csrc, g_csrc);

    static bool attr_done = false;
    if (!attr_done) {
        cudaFuncSetAttribute(gemm_pipe<false>, cudaFuncAttributeMaxDynamicSharedMemorySize, SMEM_BYTES);
        cudaFuncSetAttribute(gemm_pipe<true>,  cudaFuncAttributeMaxDynamicSharedMemorySize, SMEM_BYTES);
        attr_done = true;
    }

    const int neBlocks = (NE + 255) / 256;
    const int lgBlocks = (NN * HH * 32 + 255) / 256;
    const int agBlocks = (NN * HH + 7) / 8;

    // ---- tf32 pre-rounding of all GEMM inputs ----
    {
        int n4 = NN * 1024 / 4;
        cvt_kernel<<<(n4 + 255) / 256, 256>>>(x, xc, n4);
        n4 = 2 * 1024 * FF / 4;
        cvt_kernel<<<(n4 + 255) / 256, 256>>>(W[0], w0c, n4);
        n4 = 2 * FF * FF / 4;
        cvt_kernel<<<(n4 + 255) / 256, 256>>>(W[1], w1c, n4);
        cvt_kernel<<<(n4 + 255) / 256, 256>>>(W[2], w2c, n4);
        pad_wout_kernel<<<(FF * NOUTP + 255) / 256, 256>>>(Wout, woc);
    }

    // ---- Build CSR for both edge types ----
    for (int t = 0; t < 2; t++) {
        int* rpt = rp + t * (NN + 1);
        int* cst = csrc + t * NE;
        cudaMemsetAsync(deg, 0, NN * sizeof(int), 0);
        hist_kernel<<<neBlocks, 256>>>(dst[t], deg);
        scan_kernel<<<1, 1024>>>(deg, rpt, cur);
        scatter_kernel<<<neBlocks, 256>>>(src[t], dst[t], cur, cst);
    }

    const float* hin = xc;
    float* houts[3] = {h1, h2, h1};
    const float* Wc[3] = {w0c, w1c, w2c};
    const int Ks[3] = {1024, 512, 512};

    const int gy = (NN + BM - 1) / BM;

    for (int L = 0; L < 3; L++) {
        float* hout = houts[L];
        for (int t = 0; t < 2; t++) {
            const float* Wt = Wc[L] + (size_t)t * Ks[L] * FF;
            dim3 grid(FF / BN, gy);
            gemm_pipe<false><<<grid, 256, SMEM_BYTES>>>(hin, Wt, feat, NN, FF, FF, Ks[L], nullptr);

            logits_kernel<<<lgBlocks, 256>>>(feat, al[L] + t * FF, ar[L] + t * FF, el, er);

            aggr_fused_kernel<<<agBlocks, 256>>>(rp + t * (NN + 1), csrc + t * NE,
                                                 el, er, feat, bb[L] + t * FF, hout,
                                                 (L < 2) ? 1 : 0, (t == 0) ? 1 : 0);
        }
        hin = hout;
    }

    dim3 gridF((NOUT + BN - 1) / BN, gy);
    gemm_pipe<true><<<gridF, 256, SMEM_BYTES>>>(hin, woc, out, NN, NOUT, NOUTP, FF, bout);
}

// round 7
// speedup vs baseline: 3.8702x; 1.1347x over previous
#include <cuda_runtime.h>
#include <math.h>
#include <stdint.h>

// Problem constants (fixed-shape problem)
#define NN 40000      // nodes
#define NE 150000     // edges per type
#define HH 4          // heads
#define DD 128        // per-head dim
#define FF 512        // HH*DD
#define FF2 1024      // both edge types concatenated
#define NOUT 2983
#define NOUTP 2984    // padded (16B-aligned rows for cp.async)

// ---------------------------------------------------------------------------
// Scratch (device globals; no allocation allowed)
// ---------------------------------------------------------------------------
__device__ float g_feat[(size_t)NN * FF2];           // both types per layer
__device__ float g_h32 [(size_t)NN * FF];            // type-0 partial
__device__ float g_h1  [(size_t)NN * FF];
__device__ float g_h2  [(size_t)NN * FF];
__device__ float g_xc  [(size_t)NN * 1024];          // tf32-rounded x
__device__ float g_w0  [1024 * FF2];                 // concat [K,1024] tf32
__device__ float g_w1  [512 * FF2];
__device__ float g_w2  [512 * FF2];
__device__ float g_wo  [FF * NOUTP];                 // tf32, padded Wout
__device__ float g_el  [NN * HH];
__device__ float g_er  [NN * HH];
__device__ int   g_deg [NN];
__device__ int   g_cur [NN];
__device__ int   g_rp  [2][NN + 1];
__device__ int   g_csrc[2][NE];

// ---------------------------------------------------------------------------
// Helpers
// ---------------------------------------------------------------------------
__device__ __forceinline__ float to_tf32(float x)
{
    unsigned r;
    asm("cvt.rna.tf32.f32 %0, %1;" : "=r"(r) : "f"(x));
    return __uint_as_float(r);
}

__device__ __forceinline__ void mma_tf32(float c[4],
                                         float a0, float a1, float a2, float a3,
                                         float b0, float b1)
{
    asm volatile(
        "mma.sync.aligned.m16n8k8.row.col.f32.tf32.tf32.f32 "
        "{%0,%1,%2,%3}, {%4,%5,%6,%7}, {%8,%9}, {%0,%1,%2,%3};\n"
        : "+f"(c[0]), "+f"(c[1]), "+f"(c[2]), "+f"(c[3])
        : "r"(__float_as_uint(a0)), "r"(__float_as_uint(a1)),
          "r"(__float_as_uint(a2)), "r"(__float_as_uint(a3)),
          "r"(__float_as_uint(b0)), "r"(__float_as_uint(b1)));
}

__device__ __forceinline__ void cp_async16(uint32_t saddr, const void* gptr, int bytes)
{
    asm volatile("cp.async.cg.shared.global [%0], [%1], 16, %2;\n"
                 :: "r"(saddr), "l"(gptr), "r"(bytes));
}
__device__ __forceinline__ void cp_commit()
{
    asm volatile("cp.async.commit_group;\n");
}
__device__ __forceinline__ void cp_wait2()
{
    asm volatile("cp.async.wait_group 2;\n" ::: "memory");
}

// ---------------------------------------------------------------------------
// TF32 tensor-core GEMM, cp.async 4-stage pipeline, BK=32.
// C[M,Ncols] = A[M,K] @ B[K,NB] (row-major), Ncols <= NB.
// Inputs pre-rounded to tf32. BM=BN=128, 256 threads, warp tile 64x32.
// AS_LD=36 / BS_LD=136: both fragment read patterns are bank-conflict-free.
// ---------------------------------------------------------------------------
#define BM 128
#define BN 128
#define BKK 32
#define STAGES 4
#define AS_LD 36
#define BS_LD 136
#define A_FLOATS (BM * AS_LD)                 // 4608
#define B_FLOATS (BKK * BS_LD)                // 4352
#define STG_FLOATS (A_FLOATS + B_FLOATS)      // 8960
#define SMEM_BYTES (STAGES * STG_FLOATS * 4)  // 143360

extern __shared__ float smem_dyn[];

template <bool ADD_BIAS>
__global__ __launch_bounds__(256)
void gemm_pipe(const float* __restrict__ A, const float* __restrict__ B,
               float* __restrict__ C, int M, int Ncols, int NB, int K,
               const float* __restrict__ bias)
{
    const int tid  = threadIdx.x;
    const int wid  = tid >> 5;
    const int lane = tid & 31;
    const int wm   = wid & 1;
    const int wn   = wid >> 1;
    const int g    = lane >> 2;
    const int q    = lane & 3;

    const int bm = blockIdx.y * BM;
    const int bn = blockIdx.x * BN;

    const uint32_t sbase = (uint32_t)__cvta_generic_to_shared(smem_dyn);

    float c[4][4][4];
    #pragma unroll
    for (int i = 0; i < 4; i++)
        #pragma unroll
        for (int j = 0; j < 4; j++)
            #pragma unroll
            for (int r = 0; r < 4; r++) c[i][j][r] = 0.f;

    const int nt = K / BKK;

    auto load_stage = [&](int s, int t) {
        const int k0 = t * BKK;
        const uint32_t ss = sbase + (uint32_t)(s * STG_FLOATS) * 4u;
        #pragma unroll
        for (int i = 0; i < 4; i++) {
            int f   = i * 256 + tid;          // 0..1023
            int row = f >> 3;                 // 0..127
            int kc  = (f & 7) * 4;            // 0..28
            int m   = bm + row;
            const float* ga = (m < M) ? (A + (size_t)m * K + k0 + kc) : A;
            cp_async16(ss + (uint32_t)(row * AS_LD + kc) * 4u, ga, (m < M) ? 16 : 0);
        }
        #pragma unroll
        for (int i = 0; i < 4; i++) {
            int f    = i * 256 + tid;         // 0..1023
            int brow = f >> 5;                // 0..31
            int bcol = (f & 31) * 4;          // 0..124
            int n    = bn + bcol;
            int rem  = NB - n;
            int bytes = rem >= 4 ? 16 : (rem > 0 ? rem * 4 : 0);
            const float* gb = (bytes > 0) ? (B + (size_t)(k0 + brow) * NB + n) : B;
            cp_async16(ss + (uint32_t)(A_FLOATS + brow * BS_LD + bcol) * 4u, gb, bytes);
        }
        cp_commit();
    };

    #pragma unroll
    for (int s = 0; s < STAGES - 1; s++)
        load_stage(s, s);

    for (int t = 0; t < nt; t++) {
        cp_wait2();
        __syncthreads();

        const float* As = smem_dyn + (t & 3) * STG_FLOATS;
        const float* Bs = As + A_FLOATS;

        #pragma unroll
        for (int ks = 0; ks < 4; ks++) {
            const int kb = ks * 8;
            float a[4][4], b[4][2];
            #pragma unroll
            for (int mi = 0; mi < 4; mi++) {
                int r = wm * 64 + mi * 16 + g;
                a[mi][0] = As[(r    ) * AS_LD + kb + q];
                a[mi][1] = As[(r + 8) * AS_LD + kb + q];
                a[mi][2] = As[(r    ) * AS_LD + kb + q + 4];
                a[mi][3] = As[(r + 8) * AS_LD + kb + q + 4];
            }
            #pragma unroll
            for (int nj = 0; nj < 4; nj++) {
                int cn = wn * 32 + nj * 8 + g;
                b[nj][0] = Bs[(kb + q    ) * BS_LD + cn];
                b[nj][1] = Bs[(kb + q + 4) * BS_LD + cn];
            }
            #pragma unroll
            for (int mi = 0; mi < 4; mi++)
                #pragma unroll
                for (int nj = 0; nj < 4; nj++)
                    mma_tf32(c[mi][nj], a[mi][0], a[mi][1], a[mi][2], a[mi][3],
                             b[nj][0], b[nj][1]);
        }

        if (t + STAGES - 1 < nt)
            load_stage((t + STAGES - 1) & 3, t + STAGES - 1);
        else
            cp_commit();
    }

    #pragma unroll
    for (int mi = 0; mi < 4; mi++) {
        int row0 = bm + wm * 64 + mi * 16 + g;
        #pragma unroll
        for (int nj = 0; nj < 4; nj++) {
            int col0 = bn + wn * 32 + nj * 8 + 2 * q;
            #pragma unroll
            for (int r = 0; r < 4; r++) {
                int row = row0 + (r >= 2 ? 8 : 0);
                int col = col0 + (r & 1);
                if (row < M && col < Ncols) {
                    float v = c[mi][nj][r];
                    if (ADD_BIAS) v += bias[col];
                    C[(size_t)row * Ncols + col] = v;
                }
            }
        }
    }
}

// ---------------------------------------------------------------------------
// tf32 pre-rounding / weight concat converts
// ---------------------------------------------------------------------------
__global__ void cvt_kernel(const float* __restrict__ in, float* __restrict__ out, int n4)
{
    int i = blockIdx.x * blockDim.x + threadIdx.x;
    if (i >= n4) return;
    float4 v = reinterpret_cast<const float4*>(in)[i];
    v.x = to_tf32(v.x); v.y = to_tf32(v.y);
    v.z = to_tf32(v.z); v.w = to_tf32(v.w);
    reinterpret_cast<float4*>(out)[i] = v;
}

// in: [2, K, 512] -> out: [K, 1024] with cols [t*512 + n], tf32-rounded
__global__ void wcat_kernel(const float* __restrict__ in, float* __restrict__ out, int K)
{
    int i = blockIdx.x * blockDim.x + threadIdx.x;
    if (i >= K * FF2) return;
    int k = i >> 10;
    int c = i & 1023;
    int t = c >> 9;
    int n = c & 511;
    out[i] = to_tf32(in[((size_t)t * K + k) * 512 + n]);
}

__global__ void pad_wout_kernel(const float* __restrict__ w, float* __restrict__ o)
{
    int i = blockIdx.x * blockDim.x + threadIdx.x;
    if (i >= FF * NOUTP) return;
    int r = i / NOUTP, c = i - r * NOUTP;
    o[i] = (c < NOUT) ? to_tf32(w[r * NOUT + c]) : 0.f;
}

// ---------------------------------------------------------------------------
// CSR construction
// ---------------------------------------------------------------------------
__global__ void hist_kernel(const int* __restrict__ dst, int* __restrict__ deg)
{
    int i = blockIdx.x * blockDim.x + threadIdx.x;
    if (i < NE) atomicAdd(&deg[dst[i]], 1);
}

__global__ __launch_bounds__(1024)
void scan_kernel(const int* __restrict__ deg, int* __restrict__ rp,
                 int* __restrict__ cur)
{
    const int CH = 40;
    __shared__ int sm[1024];
    int tid = threadIdx.x;
    int start = tid * CH;

    int sum = 0;
    #pragma unroll 4
    for (int j = 0; j < CH; j++) {
        int i = start + j;
        if (i < NN) sum += deg[i];
    }
    sm[tid] = sum;
    __syncthreads();
    for (int off = 1; off < 1024; off <<= 1) {
        int t = (tid >= off) ? sm[tid - off] : 0;
        __syncthreads();
        sm[tid] += t;
        __syncthreads();
    }
    int run = sm[tid] - sum;
    for (int j = 0; j < CH; j++) {
        int i = start + j;
        if (i < NN) {
            rp[i]  = run;
            cur[i] = run;
            run += deg[i];
        }
    }
    if (tid == 1023) rp[NN] = sm[1023];
}

__global__ void scatter_kernel(const int* __restrict__ src, const int* __restrict__ dst,
                               int* __restrict__ cur, int* __restrict__ csrc)
{
    int i = blockIdx.x * blockDim.x + threadIdx.x;
    if (i < NE) {
        int p = atomicAdd(&cur[dst[i]], 1);
        csrc[p] = src[i];
    }
}

// ---------------------------------------------------------------------------
// Attention logits: one warp per (node, head). feat row stride = FF2.
// ---------------------------------------------------------------------------
__global__ void logits_kernel(const float* __restrict__ feat,
                              const float* __restrict__ al,
                              const float* __restrict__ ar,
                              float* __restrict__ el, float* __restrict__ er)
{
    int gw   = (blockIdx.x * blockDim.x + threadIdx.x) >> 5;
    int lane = threadIdx.x & 31;
    if (gw >= NN * HH) return;
    int n = gw >> 2;
    int h = gw & 3;

    float4 fv = reinterpret_cast<const float4*>(feat + (size_t)n * FF2 + h * DD)[lane];
    float4 av = reinterpret_cast<const float4*>(al + h * DD)[lane];
    float4 rv = reinterpret_cast<const float4*>(ar + h * DD)[lane];

    float dl = fv.x * av.x + fv.y * av.y + fv.z * av.z + fv.w * av.w;
    float dr = fv.x * rv.x + fv.y * rv.y + fv.z * rv.z + fv.w * rv.w;
    #pragma unroll
    for (int o = 16; o; o >>= 1) {
        dl += __shfl_xor_sync(0xFFFFFFFFu, dl, o);
        dr += __shfl_xor_sync(0xFFFFFFFFu, dr, o);
    }
    if (lane == 0) { el[gw] = dl; er[gw] = dr; }
}

// ---------------------------------------------------------------------------
// Fused segment-softmax + gather-aggregate + bias + activation + hetero-sum.
// feat row stride = FF2 (pre-offset by t*512 at launch).
// mode 0: write fp32 partial into h32. mode 1: add partial, tf32-round, write hout.
// ---------------------------------------------------------------------------
__global__ __launch_bounds__(256)
void aggr_fused_kernel(const int* __restrict__ rp, const int* __restrict__ csrc,
                       const float* __restrict__ el, const float* __restrict__ er,
                       const float* __restrict__ feat, const float* __restrict__ bias,
                       float* __restrict__ h32, float* __restrict__ hout,
                       int activate, int mode)
{
    int gw   = (blockIdx.x * blockDim.x + threadIdx.x) >> 5;
    int lane = threadIdx.x & 31;
    if (gw >= NN * HH) return;
    int n = gw >> 2;
    int h = gw & 3;

    int beg = rp[n];
    int end = rp[n + 1];
    float erd = er[gw];

    float mx = -INFINITY;
    for (int i = beg + lane; i < end; i += 32) {
        int s = csrc[i];
        float v = el[s * HH + h] + erd;
        v = (v > 0.f) ? v : 0.2f * v;
        mx = fmaxf(mx, v);
    }
    #pragma unroll
    for (int o = 16; o; o >>= 1)
        mx = fmaxf(mx, __shfl_xor_sync(0xFFFFFFFFu, mx, o));

    float ss = 0.f;
    for (int i = beg + lane; i < end; i += 32) {
        int s = csrc[i];
        float v = el[s * HH + h] + erd;
        v = (v > 0.f) ? v : 0.2f * v;
        ss += __expf(v - mx);
    }
    #pragma unroll
    for (int o = 16; o; o >>= 1)
        ss += __shfl_xor_sync(0xFFFFFFFFu, ss, o);
    float inv = (end > beg) ? 1.f / ss : 0.f;

    float4 acc = make_float4(0.f, 0.f, 0.f, 0.f);
    for (int i = beg; i < end; i++) {
        int s = csrc[i];
        float v = el[s * HH + h] + erd;
        v = (v > 0.f) ? v : 0.2f * v;
        float a = __expf(v - mx) * inv;
        float4 fv = reinterpret_cast<const float4*>(feat + (size_t)s * FF2 + h * DD)[lane];
        acc.x = fmaf(a, fv.x, acc.x);
        acc.y = fmaf(a, fv.y, acc.y);
        acc.z = fmaf(a, fv.z, acc.z);
        acc.w = fmaf(a, fv.w, acc.w);
    }

    float4 b4 = reinterpret_cast<const float4*>(bias + h * DD)[lane];
    float4 o4;
    o4.x = acc.x + b4.x; o4.y = acc.y + b4.y;
    o4.z = acc.z + b4.z; o4.w = acc.w + b4.w;
    if (activate) {
        o4.x = (o4.x > 0.f) ? o4.x : 0.01f * o4.x;
        o4.y = (o4.y > 0.f) ? o4.y : 0.01f * o4.y;
        o4.z = (o4.z > 0.f) ? o4.z : 0.01f * o4.z;
        o4.w = (o4.w > 0.f) ? o4.w : 0.01f * o4.w;
    }

    size_t off = (size_t)n * FF + h * DD + lane * 4;
    if (mode == 0) {
        *reinterpret_cast<float4*>(h32 + off) = o4;
    } else {
        float4 p = *reinterpret_cast<const float4*>(h32 + off);
        o4.x = to_tf32(p.x + o4.x); o4.y = to_tf32(p.y + o4.y);
        o4.z = to_tf32(p.z + o4.z); o4.w = to_tf32(p.w + o4.w);
        *reinterpret_cast<float4*>(hout + off) = o4;
    }
}

// ---------------------------------------------------------------------------
// Launch
// ---------------------------------------------------------------------------
extern "C" void kernel_launch(void* const* d_in, const int* in_sizes, int n_in,
                              void* d_out, int out_size)
{
    const float* x = (const float*)d_in[0];
    const int* src[2] = {(const int*)d_in[1], (const int*)d_in[3]};
    const int* dst[2] = {(const int*)d_in[2], (const int*)d_in[4]};
    const float* W [3] = {(const float*)d_in[5],  (const float*)d_in[9],  (const float*)d_in[13]};
    const float* al[3] = {(const float*)d_in[6],  (const float*)d_in[10], (const float*)d_in[14]};
    const float* ar[3] = {(const float*)d_in[7],  (const float*)d_in[11], (const float*)d_in[15]};
    const float* bb[3] = {(const float*)d_in[8],  (const float*)d_in[12], (const float*)d_in[16]};
    const float* Wout = (const float*)d_in[17];
    const float* bout = (const float*)d_in[18];
    float* out = (float*)d_out;

    float *feat, *h32, *h1, *h2, *xc, *w0c, *w1c, *w2c, *woc, *el, *er;
    int *deg, *cur, *rp, *csrc;
    cudaGetSymbolAddress((void**)&feat, g_feat);
    cudaGetSymbolAddress((void**)&h32,  g_h32);
    cudaGetSymbolAddress((void**)&h1,   g_h1);
    cudaGetSymbolAddress((void**)&h2,   g_h2);
    cudaGetSymbolAddress((void**)&xc,   g_xc);
    cudaGetSymbolAddress((void**)&w0c,  g_w0);
    cudaGetSymbolAddress((void**)&w1c,  g_w1);
    cudaGetSymbolAddress((void**)&w2c,  g_w2);
    cudaGetSymbolAddress((void**)&woc,  g_wo);
    cudaGetSymbolAddress((void**)&el,   g_el);
    cudaGetSymbolAddress((void**)&er,   g_er);
    cudaGetSymbolAddress((void**)&deg,  g_deg);
    cudaGetSymbolAddress((void**)&cur,  g_cur);
    cudaGetSymbolAddress((void**)&rp,   g_rp);
    cudaGetSymbolAddress((void**)&csrc, g_csrc);

    static bool attr_done = false;
    if (!attr_done) {
        cudaFuncSetAttribute(gemm_pipe<false>, cudaFuncAttributeMaxDynamicSharedMemorySize, SMEM_BYTES);
        cudaFuncSetAttribute(gemm_pipe<true>,  cudaFuncAttributeMaxDynamicSharedMemorySize, SMEM_BYTES);
        attr_done = true;
    }

    const int neBlocks = (NE + 255) / 256;
    const int lgBlocks = (NN * HH * 32 + 255) / 256;
    const int agBlocks = (NN * HH + 7) / 8;

    // ---- tf32 pre-rounding + weight concat ----
    {
        int n4 = NN * 1024 / 4;
        cvt_kernel<<<(n4 + 255) / 256, 256>>>(x, xc, n4);
        wcat_kernel<<<(1024 * FF2 + 255) / 256, 256>>>(W[0], w0c, 1024);
        wcat_kernel<<<(512  * FF2 + 255) / 256, 256>>>(W[1], w1c, 512);
        wcat_kernel<<<(512  * FF2 + 255) / 256, 256>>>(W[2], w2c, 512);
        pad_wout_kernel<<<(FF * NOUTP + 255) / 256, 256>>>(Wout, woc);
    }

    // ---- CSR for both edge types ----
    for (int t = 0; t < 2; t++) {
        int* rpt = rp + t * (NN + 1);
        int* cst = csrc + t * NE;
        cudaMemsetAsync(deg, 0, NN * sizeof(int), 0);
        hist_kernel<<<neBlocks, 256>>>(dst[t], deg);
        scan_kernel<<<1, 1024>>>(deg, rpt, cur);
        scatter_kernel<<<neBlocks, 256>>>(src[t], dst[t], cur, cst);
    }

    const float* hin = xc;
    float* houts[3] = {h1, h2, h1};
    const float* Wc[3] = {w0c, w1c, w2c};
    const int Ks[3] = {1024, 512, 512};

    const int gy = (NN + BM - 1) / BM;   // 313

    for (int L = 0; L < 3; L++) {
        float* hout = houts[L];
        // one GEMM covering both edge types: N = 1024
        dim3 grid(FF2 / BN, gy);
        gemm_pipe<false><<<grid, 256, SMEM_BYTES>>>(hin, Wc[L], feat, NN, FF2, FF2, Ks[L], nullptr);

        for (int t = 0; t < 2; t++) {
            const float* ft = feat + t * FF;
            logits_kernel<<<lgBlocks, 256>>>(ft, al[L] + t * FF, ar[L] + t * FF, el, er);
            aggr_fused_kernel<<<agBlocks, 256>>>(rp + t * (NN + 1), csrc + t * NE,
                                                 el, er, ft, bb[L] + t * FF,
                                                 h32, hout, (L < 2) ? 1 : 0, t);
        }
        hin = hout;
    }

    dim3 gridF((NOUT + BN - 1) / BN, gy);
    gemm_pipe<true><<<gridF, 256, SMEM_BYTES>>>(hin, woc, out, NN, NOUT, NOUTP, FF, bout);
}

// round 8
// speedup vs baseline: 4.1855x; 1.0815x over previous
#include <cuda_runtime.h>
#include <math.h>
#include <stdint.h>

// Problem constants (fixed-shape problem)
#define NN 40000      // nodes
#define NE 150000     // edges per type
#define HH 4          // heads
#define DD 128        // per-head dim
#define FF 512        // HH*DD
#define FF2 1024      // both edge types concatenated
#define NOUT 2983
#define NOUTP 2984    // padded (16B-aligned rows for cp.async)

// ---------------------------------------------------------------------------
// Scratch (device globals; no allocation allowed)
// ---------------------------------------------------------------------------
__device__ float g_feat[(size_t)NN * FF2];           // both types per layer
__device__ float g_h32 [(size_t)NN * FF];            // type-0 partial
__device__ float g_h1  [(size_t)NN * FF];
__device__ float g_h2  [(size_t)NN * FF];
__device__ float g_xc  [(size_t)NN * 1024];          // tf32-rounded x
__device__ float g_w0  [1024 * FF2];                 // concat [K,1024] tf32
__device__ float g_w1  [512 * FF2];
__device__ float g_w2  [512 * FF2];
__device__ float g_wo  [FF * NOUTP];                 // tf32, padded Wout
__device__ float g_el  [NN * HH];
__device__ float g_er  [NN * HH];
__device__ int   g_deg [NN];
__device__ int   g_cur [NN];
__device__ int   g_rp  [2][NN + 1];
__device__ int   g_csrc[2][NE];

// ---------------------------------------------------------------------------
// Helpers
// ---------------------------------------------------------------------------
__device__ __forceinline__ float to_tf32(float x)
{
    unsigned r;
    asm("cvt.rna.tf32.f32 %0, %1;" : "=r"(r) : "f"(x));
    return __uint_as_float(r);
}

__device__ __forceinline__ void mma_tf32(float c[4],
                                         float a0, float a1, float a2, float a3,
                                         float b0, float b1)
{
    asm volatile(
        "mma.sync.aligned.m16n8k8.row.col.f32.tf32.tf32.f32 "
        "{%0,%1,%2,%3}, {%4,%5,%6,%7}, {%8,%9}, {%0,%1,%2,%3};\n"
        : "+f"(c[0]), "+f"(c[1]), "+f"(c[2]), "+f"(c[3])
        : "r"(__float_as_uint(a0)), "r"(__float_as_uint(a1)),
          "r"(__float_as_uint(a2)), "r"(__float_as_uint(a3)),
          "r"(__float_as_uint(b0)), "r"(__float_as_uint(b1)));
}

__device__ __forceinline__ void cp_async16(uint32_t saddr, const void* gptr, int bytes)
{
    asm volatile("cp.async.cg.shared.global [%0], [%1], 16, %2;\n"
                 :: "r"(saddr), "l"(gptr), "r"(bytes));
}
__device__ __forceinline__ void cp_commit()
{
    asm volatile("cp.async.commit_group;\n");
}
__device__ __forceinline__ void cp_wait2()
{
    asm volatile("cp.async.wait_group 2;\n" ::: "memory");
}

// ---------------------------------------------------------------------------
// TF32 tensor-core GEMM, cp.async 4-stage pipeline.
// CTA tile 128x256, BK=32, 256 threads (8 warps), warp tile 64x64.
// C[M,Ncols] = A[M,K] @ B[K,NB] (row-major), Ncols <= NB.
// AS_LD=36 / BS_LD=264: both fragment read patterns bank-conflict-free.
// ---------------------------------------------------------------------------
#define BM 128
#define BN 256
#define BKK 32
#define STAGES 4
#define AS_LD 36
#define BS_LD 264
#define A_FLOATS (BM * AS_LD)                 // 4608
#define B_FLOATS (BKK * BS_LD)                // 8448
#define STG_FLOATS (A_FLOATS + B_FLOATS)      // 13056
#define SMEM_BYTES (STAGES * STG_FLOATS * 4)  // 208896

extern __shared__ float smem_dyn[];

template <bool ADD_BIAS>
__global__ __launch_bounds__(256, 1)
void gemm_pipe(const float* __restrict__ A, const float* __restrict__ B,
               float* __restrict__ C, int M, int Ncols, int NB, int K,
               const float* __restrict__ bias)
{
    const int tid  = threadIdx.x;
    const int wid  = tid >> 5;
    const int lane = tid & 31;
    const int wm   = wid & 1;          // 2 row groups x 64
    const int wn   = wid >> 1;         // 4 col groups x 64
    const int g    = lane >> 2;
    const int q    = lane & 3;

    const int bm = blockIdx.y * BM;
    const int bn = blockIdx.x * BN;

    const uint32_t sbase = (uint32_t)__cvta_generic_to_shared(smem_dyn);

    float c[4][8][4];
    #pragma unroll
    for (int i = 0; i < 4; i++)
        #pragma unroll
        for (int j = 0; j < 8; j++)
            #pragma unroll
            for (int r = 0; r < 4; r++) c[i][j][r] = 0.f;

    const int nt = K / BKK;

    auto load_stage = [&](int s, int t) {
        const int k0 = t * BKK;
        const uint32_t ss = sbase + (uint32_t)(s * STG_FLOATS) * 4u;
        // A tile: 128 rows x 32 k = 1024 float4, 4 per thread
        #pragma unroll
        for (int i = 0; i < 4; i++) {
            int f   = i * 256 + tid;
            int row = f >> 3;                 // 0..127
            int kc  = (f & 7) * 4;            // 0..28
            int m   = bm + row;
            const float* ga = (m < M) ? (A + (size_t)m * K + k0 + kc) : A;
            cp_async16(ss + (uint32_t)(row * AS_LD + kc) * 4u, ga, (m < M) ? 16 : 0);
        }
        // B tile: 32 rows x 256 n = 2048 float4, 8 per thread
        #pragma unroll
        for (int i = 0; i < 8; i++) {
            int f    = i * 256 + tid;
            int brow = f >> 6;                // 0..31
            int bcol = (f & 63) * 4;          // 0..252
            int n    = bn + bcol;
            int rem  = NB - n;
            int bytes = rem >= 4 ? 16 : (rem > 0 ? rem * 4 : 0);
            const float* gb = (bytes > 0) ? (B + (size_t)(k0 + brow) * NB + n) : B;
            cp_async16(ss + (uint32_t)(A_FLOATS + brow * BS_LD + bcol) * 4u, gb, bytes);
        }
        cp_commit();
    };

    #pragma unroll
    for (int s = 0; s < STAGES - 1; s++)
        load_stage(s, s);

    for (int t = 0; t < nt; t++) {
        cp_wait2();
        __syncthreads();

        const float* As = smem_dyn + (t & 3) * STG_FLOATS;
        const float* Bs = As + A_FLOATS;

        #pragma unroll
        for (int ks = 0; ks < 4; ks++) {
            const int kb = ks * 8;
            float a[4][4], b[8][2];
            #pragma unroll
            for (int mi = 0; mi < 4; mi++) {
                int r = wm * 64 + mi * 16 + g;
                a[mi][0] = As[(r    ) * AS_LD + kb + q];
                a[mi][1] = As[(r + 8) * AS_LD + kb + q];
                a[mi][2] = As[(r    ) * AS_LD + kb + q + 4];
                a[mi][3] = As[(r + 8) * AS_LD + kb + q + 4];
            }
            #pragma unroll
            for (int nj = 0; nj < 8; nj++) {
                int cn = wn * 64 + nj * 8 + g;
                b[nj][0] = Bs[(kb + q    ) * BS_LD + cn];
                b[nj][1] = Bs[(kb + q + 4) * BS_LD + cn];
            }
            #pragma unroll
            for (int mi = 0; mi < 4; mi++)
                #pragma unroll
                for (int nj = 0; nj < 8; nj++)
                    mma_tf32(c[mi][nj], a[mi][0], a[mi][1], a[mi][2], a[mi][3],
                             b[nj][0], b[nj][1]);
        }

        if (t + STAGES - 1 < nt)
            load_stage((t + STAGES - 1) & 3, t + STAGES - 1);
        else
            cp_commit();
    }

    #pragma unroll
    for (int mi = 0; mi < 4; mi++) {
        int row0 = bm + wm * 64 + mi * 16 + g;
        #pragma unroll
        for (int nj = 0; nj < 8; nj++) {
            int col0 = bn + wn * 64 + nj * 8 + 2 * q;
            #pragma unroll
            for (int r = 0; r < 4; r++) {
                int row = row0 + (r >= 2 ? 8 : 0);
                int col = col0 + (r & 1);
                if (row < M && col < Ncols) {
                    float v = c[mi][nj][r];
                    if (ADD_BIAS) v += bias[col];
                    C[(size_t)row * Ncols + col] = v;
                }
            }
        }
    }
}

// ---------------------------------------------------------------------------
// tf32 pre-rounding / weight concat converts
// ---------------------------------------------------------------------------
__global__ void cvt_kernel(const float* __restrict__ in, float* __restrict__ out, int n4)
{
    int i = blockIdx.x * blockDim.x + threadIdx.x;
    if (i >= n4) return;
    float4 v = reinterpret_cast<const float4*>(in)[i];
    v.x = to_tf32(v.x); v.y = to_tf32(v.y);
    v.z = to_tf32(v.z); v.w = to_tf32(v.w);
    reinterpret_cast<float4*>(out)[i] = v;
}

// in: [2, K, 512] -> out: [K, 1024] with cols [t*512 + n], tf32-rounded
__global__ void wcat_kernel(const float* __restrict__ in, float* __restrict__ out, int K)
{
    int i = blockIdx.x * blockDim.x + threadIdx.x;
    if (i >= K * FF2) return;
    int k = i >> 10;
    int c = i & 1023;
    int t = c >> 9;
    int n = c & 511;
    out[i] = to_tf32(in[((size_t)t * K + k) * 512 + n]);
}

__global__ void pad_wout_kernel(const float* __restrict__ w, float* __restrict__ o)
{
    int i = blockIdx.x * blockDim.x + threadIdx.x;
    if (i >= FF * NOUTP) return;
    int r = i / NOUTP, c = i - r * NOUTP;
    o[i] = (c < NOUT) ? to_tf32(w[r * NOUT + c]) : 0.f;
}

// ---------------------------------------------------------------------------
// CSR construction
// ---------------------------------------------------------------------------
__global__ void hist_kernel(const int* __restrict__ dst, int* __restrict__ deg)
{
    int i = blockIdx.x * blockDim.x + threadIdx.x;
    if (i < NE) atomicAdd(&deg[dst[i]], 1);
}

__global__ __launch_bounds__(1024)
void scan_kernel(const int* __restrict__ deg, int* __restrict__ rp,
                 int* __restrict__ cur)
{
    const int CH = 40;
    __shared__ int sm[1024];
    int tid = threadIdx.x;
    int start = tid * CH;

    int sum = 0;
    #pragma unroll 4
    for (int j = 0; j < CH; j++) {
        int i = start + j;
        if (i < NN) sum += deg[i];
    }
    sm[tid] = sum;
    __syncthreads();
    for (int off = 1; off < 1024; off <<= 1) {
        int t = (tid >= off) ? sm[tid - off] : 0;
        __syncthreads();
        sm[tid] += t;
        __syncthreads();
    }
    int run = sm[tid] - sum;
    for (int j = 0; j < CH; j++) {
        int i = start + j;
        if (i < NN) {
            rp[i]  = run;
            cur[i] = run;
            run += deg[i];
        }
    }
    if (tid == 1023) rp[NN] = sm[1023];
}

__global__ void scatter_kernel(const int* __restrict__ src, const int* __restrict__ dst,
                               int* __restrict__ cur, int* __restrict__ csrc)
{
    int i = blockIdx.x * blockDim.x + threadIdx.x;
    if (i < NE) {
        int p = atomicAdd(&cur[dst[i]], 1);
        csrc[p] = src[i];
    }
}

// ---------------------------------------------------------------------------
// Attention logits: one warp per (node, head). feat row stride = FF2.
// ---------------------------------------------------------------------------
__global__ void logits_kernel(const float* __restrict__ feat,
                              const float* __restrict__ al,
                              const float* __restrict__ ar,
                              float* __restrict__ el, float* __restrict__ er)
{
    int gw   = (blockIdx.x * blockDim.x + threadIdx.x) >> 5;
    int lane = threadIdx.x & 31;
    if (gw >= NN * HH) return;
    int n = gw >> 2;
    int h = gw & 3;

    float4 fv = reinterpret_cast<const float4*>(feat + (size_t)n * FF2 + h * DD)[lane];
    float4 av = reinterpret_cast<const float4*>(al + h * DD)[lane];
    float4 rv = reinterpret_cast<const float4*>(ar + h * DD)[lane];

    float dl = fv.x * av.x + fv.y * av.y + fv.z * av.z + fv.w * av.w;
    float dr = fv.x * rv.x + fv.y * rv.y + fv.z * rv.z + fv.w * rv.w;
    #pragma unroll
    for (int o = 16; o; o >>= 1) {
        dl += __shfl_xor_sync(0xFFFFFFFFu, dl, o);
        dr += __shfl_xor_sync(0xFFFFFFFFu, dr, o);
    }
    if (lane == 0) { el[gw] = dl; er[gw] = dr; }
}

// ---------------------------------------------------------------------------
// Fused segment-softmax + gather-aggregate + bias + activation + hetero-sum.
// feat row stride = FF2 (pre-offset by t*512 at launch).
// mode 0: write fp32 partial into h32. mode 1: add partial, tf32-round, write hout.
// ---------------------------------------------------------------------------
__global__ __launch_bounds__(256)
void aggr_fused_kernel(const int* __restrict__ rp, const int* __restrict__ csrc,
                       const float* __restrict__ el, const float* __restrict__ er,
                       const float* __restrict__ feat, const float* __restrict__ bias,
                       float* __restrict__ h32, float* __restrict__ hout,
                       int activate, int mode)
{
    int gw   = (blockIdx.x * blockDim.x + threadIdx.x) >> 5;
    int lane = threadIdx.x & 31;
    if (gw >= NN * HH) return;
    int n = gw >> 2;
    int h = gw & 3;

    int beg = rp[n];
    int end = rp[n + 1];
    float erd = er[gw];

    float mx = -INFINITY;
    for (int i = beg + lane; i < end; i += 32) {
        int s = csrc[i];
        float v = el[s * HH + h] + erd;
        v = (v > 0.f) ? v : 0.2f * v;
        mx = fmaxf(mx, v);
    }
    #pragma unroll
    for (int o = 16; o; o >>= 1)
        mx = fmaxf(mx, __shfl_xor_sync(0xFFFFFFFFu, mx, o));

    float ss = 0.f;
    for (int i = beg + lane; i < end; i += 32) {
        int s = csrc[i];
        float v = el[s * HH + h] + erd;
        v = (v > 0.f) ? v : 0.2f * v;
        ss += __expf(v - mx);
    }
    #pragma unroll
    for (int o = 16; o; o >>= 1)
        ss += __shfl_xor_sync(0xFFFFFFFFu, ss, o);
    float inv = (end > beg) ? 1.f / ss : 0.f;

    float4 acc = make_float4(0.f, 0.f, 0.f, 0.f);
    for (int i = beg; i < end; i++) {
        int s = csrc[i];
        float v = el[s * HH + h] + erd;
        v = (v > 0.f) ? v : 0.2f * v;
        float a = __expf(v - mx) * inv;
        float4 fv = reinterpret_cast<const float4*>(feat + (size_t)s * FF2 + h * DD)[lane];
        acc.x = fmaf(a, fv.x, acc.x);
        acc.y = fmaf(a, fv.y, acc.y);
        acc.z = fmaf(a, fv.z, acc.z);
        acc.w = fmaf(a, fv.w, acc.w);
    }

    float4 b4 = reinterpret_cast<const float4*>(bias + h * DD)[lane];
    float4 o4;
    o4.x = acc.x + b4.x; o4.y = acc.y + b4.y;
    o4.z = acc.z + b4.z; o4.w = acc.w + b4.w;
    if (activate) {
        o4.x = (o4.x > 0.f) ? o4.x : 0.01f * o4.x;
        o4.y = (o4.y > 0.f) ? o4.y : 0.01f * o4.y;
        o4.z = (o4.z > 0.f) ? o4.z : 0.01f * o4.z;
        o4.w = (o4.w > 0.f) ? o4.w : 0.01f * o4.w;
    }

    size_t off = (size_t)n * FF + h * DD + lane * 4;
    if (mode == 0) {
        *reinterpret_cast<float4*>(h32 + off) = o4;
    } else {
        float4 p = *reinterpret_cast<const float4*>(h32 + off);
        o4.x = to_tf32(p.x + o4.x); o4.y = to_tf32(p.y + o4.y);
        o4.z = to_tf32(p.z + o4.z); o4.w = to_tf32(p.w + o4.w);
        *reinterpret_cast<float4*>(hout + off) = o4;
    }
}

// ---------------------------------------------------------------------------
// Launch
// ---------------------------------------------------------------------------
extern "C" void kernel_launch(void* const* d_in, const int* in_sizes, int n_in,
                              void* d_out, int out_size)
{
    const float* x = (const float*)d_in[0];
    const int* src[2] = {(const int*)d_in[1], (const int*)d_in[3]};
    const int* dst[2] = {(const int*)d_in[2], (const int*)d_in[4]};
    const float* W [3] = {(const float*)d_in[5],  (const float*)d_in[9],  (const float*)d_in[13]};
    const float* al[3] = {(const float*)d_in[6],  (const float*)d_in[10], (const float*)d_in[14]};
    const float* ar[3] = {(const float*)d_in[7],  (const float*)d_in[11], (const float*)d_in[15]};
    const float* bb[3] = {(const float*)d_in[8],  (const float*)d_in[12], (const float*)d_in[16]};
    const float* Wout = (const float*)d_in[17];
    const float* bout = (const float*)d_in[18];
    float* out = (float*)d_out;

    float *feat, *h32, *h1, *h2, *xc, *w0c, *w1c, *w2c, *woc, *el, *er;
    int *deg, *cur, *rp, *csrc;
    cudaGetSymbolAddress((void**)&feat, g_feat);
    cudaGetSymbolAddress((void**)&h32,  g_h32);
    cudaGetSymbolAddress((void**)&h1,   g_h1);
    cudaGetSymbolAddress((void**)&h2,   g_h2);
    cudaGetSymbolAddress((void**)&xc,   g_xc);
    cudaGetSymbolAddress((void**)&w0c,  g_w0);
    cudaGetSymbolAddress((void**)&w1c,  g_w1);
    cudaGetSymbolAddress((void**)&w2c,  g_w2);
    cudaGetSymbolAddress((void**)&woc,  g_wo);
    cudaGetSymbolAddress((void**)&el,   g_el);
    cudaGetSymbolAddress((void**)&er,   g_er);
    cudaGetSymbolAddress((void**)&deg,  g_deg);
    cudaGetSymbolAddress((void**)&cur,  g_cur);
    cudaGetSymbolAddress((void**)&rp,   g_rp);
    cudaGetSymbolAddress((void**)&csrc, g_csrc);

    static bool attr_done = false;
    if (!attr_done) {
        cudaFuncSetAttribute(gemm_pipe<false>, cudaFuncAttributeMaxDynamicSharedMemorySize, SMEM_BYTES);
        cudaFuncSetAttribute(gemm_pipe<true>,  cudaFuncAttributeMaxDynamicSharedMemorySize, SMEM_BYTES);
        attr_done = true;
    }

    const int neBlocks = (NE + 255) / 256;
    const int lgBlocks = (NN * HH * 32 + 255) / 256;
    const int agBlocks = (NN * HH + 7) / 8;

    // ---- tf32 pre-rounding + weight concat ----
    {
        int n4 = NN * 1024 / 4;
        cvt_kernel<<<(n4 + 255) / 256, 256>>>(x, xc, n4);
        wcat_kernel<<<(1024 * FF2 + 255) / 256, 256>>>(W[0], w0c, 1024);
        wcat_kernel<<<(512  * FF2 + 255) / 256, 256>>>(W[1], w1c, 512);
        wcat_kernel<<<(512  * FF2 + 255) / 256, 256>>>(W[2], w2c, 512);
        pad_wout_kernel<<<(FF * NOUTP + 255) / 256, 256>>>(Wout, woc);
    }

    // ---- CSR for both edge types ----
    for (int t = 0; t < 2; t++) {
        int* rpt = rp + t * (NN + 1);
        int* cst = csrc + t * NE;
        cudaMemsetAsync(deg, 0, NN * sizeof(int), 0);
        hist_kernel<<<neBlocks, 256>>>(dst[t], deg);
        scan_kernel<<<1, 1024>>>(deg, rpt, cur);
        scatter_kernel<<<neBlocks, 256>>>(src[t], dst[t], cur, cst);
    }

    const float* hin = xc;
    float* houts[3] = {h1, h2, h1};
    const float* Wc[3] = {w0c, w1c, w2c};
    const int Ks[3] = {1024, 512, 512};

    const int gy = (NN + BM - 1) / BM;   // 313

    for (int L = 0; L < 3; L++) {
        float* hout = houts[L];
        // one GEMM covering both edge types: N = 1024 -> 4 column blocks
        dim3 grid(FF2 / BN, gy);
        gemm_pipe<false><<<grid, 256, SMEM_BYTES>>>(hin, Wc[L], feat, NN, FF2, FF2, Ks[L], nullptr);

        for (int t = 0; t < 2; t++) {
            const float* ft = feat + t * FF;
            logits_kernel<<<lgBlocks, 256>>>(ft, al[L] + t * FF, ar[L] + t * FF, el, er);
            aggr_fused_kernel<<<agBlocks, 256>>>(rp + t * (NN + 1), csrc + t * NE,
                                                 el, er, ft, bb[L] + t * FF,
                                                 h32, hout, (L < 2) ? 1 : 0, t);
        }
        hin = hout;
    }

    dim3 gridF((NOUT + BN - 1) / BN, gy);
    gemm_pipe<true><<<gridF, 256, SMEM_BYTES>>>(hin, woc, out, NN, NOUT, NOUTP, FF, bout);
}